// round 13
// baseline (speedup 1.0000x reference)
#include <cuda_runtime.h>

#define EPSV 1e-5f
typedef unsigned long long ull;

// ---------------- shared memory layout (float offsets), 14336 floats = 56KB --
// Phase 1:
//   [0,7168)      pooled[128][56]
//     after stage B (pooled+wcrT dead): QT[4][60]@0, KT[4][60]@240,
//        VT[56][32]@480, S[56][60]@2272..5632, attnT[56][60]@5632..8992,
//        RED@8992..9024
//   [7168,11392)  wcrT[128][33]   (dead after stage B)
//   [11392,12416) vTw[32][32]
//   [12416,14336) xbuf[32][60]
// Phase 2:
//   [0,3456)      xpadA[32][9][12]   (ch16+ region reused as F-merge scratch)
//   [3456,5760)   shA[32][9][8]
//   [3424,5760)   shB (aliases shA + 32-float XPA tail; halves @3424/4592)
//   [5760,9248)   xpadB 2 halves of [16][9][12], half stride 1744
//   [9248,14000)  wres half [144][33]=4752 (reused as E-merge scratch);
//                 later w1T 2x[144][17] @9248/11696
//   [14144,14288) w2
#define POOL_OFF 0
#define QT_OFF   0
#define KT_OFF   240
#define VT_OFF   480
#define S_OFF    2272
#define ATT_OFF  5632
#define RED_OFF  8992
#define WCRT_OFF 7168
#define VTW_OFF  11392
#define XBUF_OFF 12416

#define XPA_OFF  0
#define SHA_OFF  3456
#define SHB_OFF  3424
#define XPB_OFF  5760
#define WR2_OFF  9248
#define W2_OFF   14144
#define SMEM_FLOATS 14336

#define FSCR_OFF (XPA_OFF + 1728)   // F-merge scratch (dead xpadA ch16+)

// ---------------- packed f32x2 helpers ----------------
__device__ __forceinline__ ull pk2(float x, float y) {
    ull r; asm("mov.b64 %0, {%1, %2};" : "=l"(r) : "f"(x), "f"(y)); return r;
}
__device__ __forceinline__ void up2(ull v, float& x, float& y) {
    asm("mov.b64 {%0, %1}, %2;" : "=f"(x), "=f"(y) : "l"(v));
}
__device__ __forceinline__ ull fma2(ull a, ull b, ull c) {
    ull r; asm("fma.rn.f32x2 %0, %1, %2, %3;" : "=l"(r) : "l"(a), "l"(b), "l"(c)); return r;
}
__device__ __forceinline__ ull add2(ull a, ull b) {
    ull r; asm("add.rn.f32x2 %0, %1, %2;" : "=l"(r) : "l"(a), "l"(b)); return r;
}

// 8-wide GEMM step: acc[4] += w * x[0..7], x warp-uniform (broadcast LDS.128)
// REQUIREMENT: x must be 16B-aligned (float offset % 4 == 0)
__device__ __forceinline__ void g8(ull acc[4], const float* __restrict__ x, float wv) {
    ulonglong2 A = *(const ulonglong2*)(x);
    ulonglong2 B = *(const ulonglong2*)(x + 4);
    ull wp = pk2(wv, wv);
    acc[0] = fma2(wp, A.x, acc[0]); acc[1] = fma2(wp, A.y, acc[1]);
    acc[2] = fma2(wp, B.x, acc[2]); acc[3] = fma2(wp, B.y, acc[3]);
}

// one 3-tap row application: 12 FFMA2 for 8 outputs
__device__ __forceinline__ void apply9(ull acc[4], const ull* __restrict__ W,
        const ulonglong2& E01, const ulonglong2& E23, ull E4,
        const ulonglong2& O01, const ulonglong2& O23) {
    acc[0] = fma2(W[0], E01.x, acc[0]); acc[1] = fma2(W[0], E01.y, acc[1]);
    acc[2] = fma2(W[0], E23.x, acc[2]); acc[3] = fma2(W[0], E23.y, acc[3]);
    acc[0] = fma2(W[1], O01.x, acc[0]); acc[1] = fma2(W[1], O01.y, acc[1]);
    acc[2] = fma2(W[1], O23.x, acc[2]); acc[3] = fma2(W[1], O23.y, acc[3]);
    acc[0] = fma2(W[2], E01.y, acc[0]); acc[1] = fma2(W[2], E23.x, acc[1]);
    acc[2] = fma2(W[2], E23.y, acc[2]); acc[3] = fma2(W[2], E4,    acc[3]);
}

// 3x3 conv over nch channels (channel steps xstep/sstep/wstep allow parity
// splits), output rows p0 (and p0+1 if TWO). Weights loaded once per channel.
// E4 = (x8, 0) reconstructed from O23.y (x9 is always pad-zero).
template<bool TWO>
__device__ __forceinline__ void conv_pair(ull a0[4], ull a1[4],
    const float* __restrict__ xb, const float* __restrict__ sb,
    const float* __restrict__ wb, int ws, int o, int p0, int nch,
    int xstep, int sstep, int wstep) {
    #pragma unroll 1
    for (int ch = 0; ch < nch; ++ch) {
        const float* wp = wb + ch * wstep + o;
        ull W[9];
        #pragma unroll
        for (int k = 0; k < 9; ++k) { float wv = wp[k * ws]; W[k] = pk2(wv, wv); }
        const float* xrow = xb + ch * xstep + p0 * 12;
        const float* srow = sb + ch * sstep + p0 * 8;
        #pragma unroll
        for (int r = 0; r < (TWO ? 4 : 3); ++r) {
            ulonglong2 E01 = *(const ulonglong2*)(xrow + r * 12);
            ulonglong2 E23 = *(const ulonglong2*)(xrow + r * 12 + 4);
            ulonglong2 O01 = *(const ulonglong2*)(srow + r * 8);
            ulonglong2 O23 = *(const ulonglong2*)(srow + r * 8 + 4);
            ull E4 = O23.y >> 32;                 // (x8, 0)
            if (r < 3)         apply9(a0, W + 3 * r,       E01, E23, E4, O01, O23);
            if (TWO && r >= 1) apply9(a1, W + 3 * (r - 1), E01, E23, E4, O01, O23);
        }
    }
}

__global__ void __launch_bounds__(256, 4) occ_fused_kernel(
    const float* __restrict__ mg,
    const float* __restrict__ w_cr, const float* __restrict__ b_cr,
    const float* __restrict__ bnr_w, const float* __restrict__ bnr_b,
    const float* __restrict__ bnr_m, const float* __restrict__ bnr_v,
    const float* __restrict__ q_w,  const float* __restrict__ q_b,
    const float* __restrict__ k_w,  const float* __restrict__ k_b,
    const float* __restrict__ v_w,  const float* __restrict__ v_b,
    const float* __restrict__ gamma,
    const float* __restrict__ ln_w, const float* __restrict__ ln_b,
    const float* __restrict__ w_res, const float* __restrict__ b_res,
    const float* __restrict__ bnres_w, const float* __restrict__ bnres_b,
    const float* __restrict__ bnres_m, const float* __restrict__ bnres_v,
    const float* __restrict__ w1,  const float* __restrict__ b1,
    const float* __restrict__ bn1_w, const float* __restrict__ bn1_b,
    const float* __restrict__ bn1_m, const float* __restrict__ bn1_v,
    const float* __restrict__ w2,  const float* __restrict__ b2,
    float* __restrict__ out)
{
    extern __shared__ float sm[];
    const int t = threadIdx.x;
    const int b = blockIdx.x;
    const int w = t >> 5;
    const int lane = t & 31;
    float* red = sm + RED_OFF;

    // ============ Stage A: adaptive pool 16x16 -> 7x8 + stage phase-1 weights ======
    {
        const float* in = mg + (size_t)b * 32768;
        int c = t / 56, s = t - c * 56;
        for (int idx = t; idx < 7168; idx += 256) {
            int p = s >> 3, q = s & 7;
            int r0 = (p * 147) >> 6;
            int r1 = ((p + 1) * 16 + 6) / 7;
            const float2* bp = (const float2*)(in + c * 256 + q * 2);
            float acc = 0.f;
            for (int r = r0; r < r1; ++r) { float2 v2 = bp[r * 8]; acc += v2.x + v2.y; }
            sm[POOL_OFF + idx] = acc * (0.5f / (float)(r1 - r0));
            s += 32; c += 4; if (s >= 56) { s -= 56; ++c; }
        }
        for (int idx = t; idx < 4096; idx += 256) {       // wcrT[c][o], stride 33
            int o = idx >> 7, cc = idx & 127;
            sm[WCRT_OFF + cc * 33 + o] = w_cr[idx];
        }
        for (int idx = t; idx < 1024; idx += 256) {       // vTw[in][o], stride 32
            int in2 = idx >> 5, o = idx & 31;
            sm[VTW_OFF + in2 * 32 + o] = v_w[o * 32 + in2];
        }
    }
    __syncthreads();

    // ============ Stage B: 1x1 128->32 + BN + ReLU. warp=p, lane=o ============
    if (w < 7) {
        ull a[4] = {0,0,0,0};
        const float* xb = sm + POOL_OFF + w * 8;
        const float* wc = sm + WCRT_OFF + lane;
        #pragma unroll 4
        for (int c = 0; c < 128; ++c)
            g8(a, xb + c * 56, wc[c * 33]);
        float sc = bnr_w[lane] * rsqrtf(bnr_v[lane] + EPSV);
        float bi = fmaf(b_cr[lane], sc, bnr_b[lane] - bnr_m[lane] * sc);
        float r[8];
        up2(a[0],r[0],r[1]); up2(a[1],r[2],r[3]); up2(a[2],r[4],r[5]); up2(a[3],r[6],r[7]);
        float* dst = sm + XBUF_OFF + lane * 60 + w * 8;
        #pragma unroll
        for (int q = 0; q < 8; ++q) dst[q] = fmaxf(fmaf(r[q], sc, bi), 0.f);
    }
    __syncthreads();

    // ============ Stage C1: v (warps 0-6), q & k (warp 7, weights via gmem) =======
    if (w < 7) {
        float bias = v_b[lane];
        ull a[4]; a[0]=a[1]=a[2]=a[3]=pk2(bias,bias);
        const float* xb = sm + XBUF_OFF + w * 8;
        const float* wv2p = sm + VTW_OFF + lane;
        #pragma unroll 4
        for (int in2 = 0; in2 < 32; ++in2)
            g8(a, xb + in2 * 60, wv2p[in2 * 32]);
        float r[8];
        up2(a[0],r[0],r[1]); up2(a[1],r[2],r[3]); up2(a[2],r[4],r[5]); up2(a[3],r[6],r[7]);
        #pragma unroll
        for (int q = 0; q < 8; ++q) sm[VT_OFF + (w * 8 + q) * 32 + lane] = r[q];
    } else if (lane < 28) {
        int d = lane / 7, p = lane - d * 7;
        const float* xb = sm + XBUF_OFF + p * 8;
        #pragma unroll
        for (int pass = 0; pass < 2; ++pass) {
            const float* W = (pass ? k_w : q_w) + d * 32;
            float bias = pass ? k_b[d] : q_b[d];
            ull a[4]; a[0]=a[1]=a[2]=a[3]=pk2(bias,bias);
            for (int in2 = 0; in2 < 32; ++in2) g8(a, xb + in2 * 60, __ldg(W + in2));
            float r[8];
            up2(a[0],r[0],r[1]); up2(a[1],r[2],r[3]); up2(a[2],r[4],r[5]); up2(a[3],r[6],r[7]);
            float* dst = sm + (pass ? KT_OFF : QT_OFF) + d * 60 + p * 8;
            #pragma unroll
            for (int q = 0; q < 8; ++q) dst[q] = r[q];
        }
    }
    __syncthreads();

    // ============ Stage C2: S[i][j] = sum_d q[d][i] k[d][j] ============
    if (w < 7) {
        int i0 = w * 8;
        #pragma unroll
        for (int seg = 0; seg < 2; ++seg) {
            int j = seg * 32 + lane;
            if (j < 56) {
                ull a[4] = {0,0,0,0};
                #pragma unroll
                for (int d = 0; d < 4; ++d)
                    g8(a, sm + QT_OFF + d * 60 + i0, sm[KT_OFF + d * 60 + j]);
                float r[8];
                up2(a[0],r[0],r[1]); up2(a[1],r[2],r[3]); up2(a[2],r[4],r[5]); up2(a[3],r[6],r[7]);
                #pragma unroll
                for (int q = 0; q < 8; ++q) sm[S_OFF + (i0 + q) * 60 + j] = r[q];
            }
        }
    }
    __syncthreads();

    // ============ softmax: 8 warps x 7 rows, shfl reductions, write attnT[j][i] ===
    {
        int i0 = w * 7;
        #pragma unroll 1
        for (int rr = 0; rr < 7; ++rr) {
            int i = i0 + rr;
            const float* row = sm + S_OFF + i * 60;
            float v0 = row[lane];
            float v1 = (lane < 24) ? row[32 + lane] : -1e30f;
            float m = fmaxf(v0, v1);
            #pragma unroll
            for (int off = 16; off; off >>= 1)
                m = fmaxf(m, __shfl_xor_sync(0xffffffffu, m, off));
            float e0 = __expf(v0 - m);
            float e1 = (lane < 24) ? __expf(v1 - m) : 0.f;
            float ssum = e0 + e1;
            #pragma unroll
            for (int off = 16; off; off >>= 1)
                ssum += __shfl_xor_sync(0xffffffffu, ssum, off);
            float inv = 1.f / ssum;
            sm[ATT_OFF + lane * 60 + i] = e0 * inv;
            if (lane < 24) sm[ATT_OFF + (32 + lane) * 60 + i] = e1 * inv;
        }
    }
    __syncthreads();

    // ============ Stage C3: out[c][i] = sum_j v[j][c]*attnT[j][i]; x += gamma*out ==
    if (w < 7) {
        int i0 = w * 8;
        ull a[4] = {0,0,0,0};
        #pragma unroll 4
        for (int j = 0; j < 56; ++j)
            g8(a, sm + ATT_OFF + j * 60 + i0, sm[VT_OFF + j * 32 + lane]);
        float r[8];
        up2(a[0],r[0],r[1]); up2(a[1],r[2],r[3]); up2(a[2],r[4],r[5]); up2(a[3],r[6],r[7]);
        float g = gamma[0];
        float* xr = sm + XBUF_OFF + lane * 60 + i0;
        #pragma unroll
        for (int q = 0; q < 8; ++q) xr[q] = fmaf(g, r[q], xr[q]);
    }
    __syncthreads();

    // ============ Stage D: LayerNorm over 1792 ============
    float vals[7];
    {
        float s1 = 0.f, s2 = 0.f;
        int c = t / 56, s = t - c * 56;
        #pragma unroll
        for (int k = 0; k < 7; ++k) {
            float x = sm[XBUF_OFF + c * 60 + s];
            vals[k] = x; s1 += x; s2 = fmaf(x, x, s2);
            s += 32; c += 4; if (s >= 56) { s -= 56; ++c; }
        }
        #pragma unroll
        for (int off = 16; off; off >>= 1) {
            s1 += __shfl_xor_sync(0xffffffffu, s1, off);
            s2 += __shfl_xor_sync(0xffffffffu, s2, off);
        }
        if (lane == 0) { red[w] = s1; red[8 + w] = s2; }
        __syncthreads();
        if (t == 0) {
            float S1 = 0.f, S2 = 0.f;
            for (int k = 0; k < 8; ++k) { S1 += red[k]; S2 += red[8 + k]; }
            float mu = S1 * (1.f / 1792.f);
            float var = S2 * (1.f / 1792.f) - mu * mu;
            red[16] = mu; red[17] = rsqrtf(var + EPSV);
        }
        __syncthreads();
        float mu = red[16], inv = red[17];
        #pragma unroll
        for (int k = 0; k < 7; ++k) {
            int v = t + k * 256;
            vals[k] = (vals[k] - mu) * inv * ln_w[v] + ln_b[v];
        }
    }
    __syncthreads();   // all phase-1 activation reads done

    // zero phase-2 activation region [0,9248) + stage w_res half 1
    {
        float4 z4 = make_float4(0.f, 0.f, 0.f, 0.f);
        float4* z = (float4*)sm;
        for (int idx = t; idx < 2312; idx += 256) z[idx] = z4;
        for (int idx = t; idx < 4608; idx += 256) {
            int o = idx / 144, r = idx - o * 144;
            sm[WR2_OFF + r * 33 + o] = w_res[o * 288 + r];
        }
    }
    __syncthreads();
    {
        int c = t / 56, s = t - c * 56;
        #pragma unroll
        for (int k = 0; k < 7; ++k) {   // scatter LN output into xpadA + shifted shA
            int p = s >> 3, q = s & 7;
            sm[XPA_OFF + c * 108 + (p + 1) * 12 + (q + 1)] = vals[k];
            sm[SHA_OFF + c * 72 + (p + 1) * 8 + q] = vals[k];
            s += 32; c += 4; if (s >= 56) { s -= 56; ++c; }
        }
    }
    __syncthreads();

    // ============ Stage E: 3x3 conv 32->32, 8 warps: row-pair (g) x parity (par) ==
    const int g   = w & 3;
    const int par = w >> 2;
    const int p0  = (g < 3) ? 2 * g : 6;
    ull ea0[4] = {0,0,0,0}, ea1[4] = {0,0,0,0};
    {   // half 1: input channels par, par+2, ..., par+14
        const float* xb = sm + XPA_OFF + par * 108;
        const float* sb = sm + SHA_OFF + par * 72;
        const float* wb = sm + WR2_OFF + par * 297;   // par*9*33
        if (g < 3) conv_pair<true >(ea0, ea1, xb, sb, wb, 33, lane, p0, 8, 216, 144, 594);
        else       conv_pair<false>(ea0, ea1, xb, sb, wb, 33, lane, 6,  8, 216, 144, 594);
    }
    __syncthreads();
    for (int idx = t; idx < 4608; idx += 256) {    // stage w_res half 2
        int o = idx / 144, r = idx - o * 144;
        sm[WR2_OFF + r * 33 + o] = w_res[o * 288 + 144 + r];
    }
    __syncthreads();
    {   // half 2: input channels 16+par, 16+par+2, ...
        const float* xb = sm + XPA_OFF + (16 + par) * 108;
        const float* sb = sm + SHA_OFF + (16 + par) * 72;
        const float* wb = sm + WR2_OFF + par * 297;
        if (g < 3) conv_pair<true >(ea0, ea1, xb, sb, wb, 33, lane, p0, 8, 216, 144, 594);
        else       conv_pair<false>(ea0, ea1, xb, sb, wb, 33, lane, 6,  8, 216, 144, 594);
    }
    __syncthreads();   // conv reads of WR2 / shA done

    // E-merge phase 1: warps 4-7 park partials in dead WR2; warps 0-3 do shB pads+w2
    if (w >= 4) {
        float* s = sm + WR2_OFF + g * 640 + lane * 20;
        ((ulonglong2*)s)[0]       = make_ulonglong2(ea0[0], ea0[1]);
        ((ulonglong2*)(s + 4))[0] = make_ulonglong2(ea0[2], ea0[3]);
        if (g < 3) {
            ((ulonglong2*)(s + 8))[0]  = make_ulonglong2(ea1[0], ea1[1]);
            ((ulonglong2*)(s + 12))[0] = make_ulonglong2(ea1[2], ea1[3]);
        }
    } else {
        for (int idx = t; idx < 144; idx += 128) sm[W2_OFF + idx] = w2[idx];
    }
    __syncthreads();

    // E-merge phase 2: warps 0-3 add partner partials + BN + ReLU + residual -> regs
    // (NO shB/xpadB writes here: shB overlaps xpadA tail read as residual by g=3.
    //  All residual reads complete before the barrier below, as in round 10.)
    float er0[8], er1[8];
    if (w < 4) {
        const float* s = sm + WR2_OFF + g * 640 + lane * 20;
        {
            ulonglong2 pA = ((const ulonglong2*)s)[0];
            ulonglong2 pB = ((const ulonglong2*)(s + 4))[0];
            ea0[0] = add2(ea0[0], pA.x); ea0[1] = add2(ea0[1], pA.y);
            ea0[2] = add2(ea0[2], pB.x); ea0[3] = add2(ea0[3], pB.y);
        }
        if (g < 3) {
            ulonglong2 pA = ((const ulonglong2*)(s + 8))[0];
            ulonglong2 pB = ((const ulonglong2*)(s + 12))[0];
            ea1[0] = add2(ea1[0], pA.x); ea1[1] = add2(ea1[1], pA.y);
            ea1[2] = add2(ea1[2], pB.x); ea1[3] = add2(ea1[3], pB.y);
        }
        float sc = bnres_w[lane] * rsqrtf(bnres_v[lane] + EPSV);
        float bi = fmaf(b_res[lane], sc, bnres_b[lane] - bnres_m[lane] * sc);
        const float* rs0 = sm + XPA_OFF + lane * 108 + (p0 + 1) * 12 + 1;
        float r0[8];
        up2(ea0[0],r0[0],r0[1]); up2(ea0[1],r0[2],r0[3]);
        up2(ea0[2],r0[4],r0[5]); up2(ea0[3],r0[6],r0[7]);
        #pragma unroll
        for (int q = 0; q < 8; ++q) er0[q] = fmaxf(fmaf(r0[q], sc, bi), 0.f) + rs0[q];
        if (g < 3) {
            float r1[8];
            up2(ea1[0],r1[0],r1[1]); up2(ea1[1],r1[2],r1[3]);
            up2(ea1[2],r1[4],r1[5]); up2(ea1[3],r1[6],r1[7]);
            const float* rs1 = rs0 + 12;
            #pragma unroll
            for (int q = 0; q < 8; ++q) er1[q] = fmaxf(fmaf(r1[q], sc, bi), 0.f) + rs1[q];
        }
    }
    __syncthreads();   // all residual/shA reads + scratch reads done

    // write stage-E rows into xpadB/shB, zero shB pad rows, stage w1T concurrently
    if (w < 4) {
        int hoff = (lane >> 4) * 16;
        float* db0 = sm + XPB_OFF + lane * 108 + hoff + (p0 + 1) * 12 + 1;
        float* sb0 = sm + SHB_OFF + lane * 72 + hoff + (p0 + 1) * 8;
        #pragma unroll
        for (int q = 0; q < 8; ++q) { db0[q] = er0[q]; sb0[q] = er0[q]; }
        if (g < 3) {
            #pragma unroll
            for (int q = 0; q < 8; ++q) { db0[12 + q] = er1[q]; sb0[8 + q] = er1[q]; }
        }
    } else {
        for (int idx = t - 128; idx < 512; idx += 128) {   // zero shB pad rows 0 & 8
            int ch = idx >> 4, rem = idx & 15;
            int rowoff = (rem & 8) ? 64 : 0, q = rem & 7;
            sm[SHB_OFF + ch * 72 + (ch >> 4) * 16 + rowoff + q] = 0.f;
        }
    }
    for (int idx = t; idx < 4608; idx += 256) {    // w1T two halves, stride 17
        int o = idx / 288, rr = idx - o * 288;
        int half = (rr >= 144) ? 1 : 0, rp = rr - half * 144;
        sm[WR2_OFF + half * 2448 + rp * 17 + o] = w1[idx];
    }
    __syncthreads();

    // ============ Stage F: 3x3 conv 32->16, 8 warps: rows x parity, lane halves ===
    {
        int o16 = lane & 15, half = lane >> 4;
        const float* xb = sm + XPB_OFF + half * 1744 + par * 108;
        const float* sb = sm + SHB_OFF + half * 1168 + par * 72;
        const float* wb = sm + WR2_OFF + half * 2448 + par * 153;  // par*9*17
        ull fa0[4] = {0,0,0,0}, fa1[4] = {0,0,0,0};
        if (g < 3) conv_pair<true >(fa0, fa1, xb, sb, wb, 17, o16, p0, 8, 216, 144, 306);
        else       conv_pair<false>(fa0, fa1, xb, sb, wb, 17, o16, 6,  8, 216, 144, 306);
        #pragma unroll
        for (int m = 0; m < 4; ++m) {
            fa0[m] = add2(fa0[m], __shfl_xor_sync(0xffffffffu, fa0[m], 16));
            fa1[m] = add2(fa1[m], __shfl_xor_sync(0xffffffffu, fa1[m], 16));
        }
        if (w >= 4 && lane < 16) {   // park parity-1 partials in dead xpadA ch16+
            float* s = sm + FSCR_OFF + g * 320 + lane * 20;
            ((ulonglong2*)s)[0]       = make_ulonglong2(fa0[0], fa0[1]);
            ((ulonglong2*)(s + 4))[0] = make_ulonglong2(fa0[2], fa0[3]);
            if (g < 3) {
                ((ulonglong2*)(s + 8))[0]  = make_ulonglong2(fa1[0], fa1[1]);
                ((ulonglong2*)(s + 12))[0] = make_ulonglong2(fa1[2], fa1[3]);
            }
        }
        __syncthreads();
        if (w < 4 && lane < 16) {
            const float* s = sm + FSCR_OFF + g * 320 + lane * 20;
            {
                ulonglong2 pA = ((const ulonglong2*)s)[0];
                ulonglong2 pB = ((const ulonglong2*)(s + 4))[0];
                fa0[0] = add2(fa0[0], pA.x); fa0[1] = add2(fa0[1], pA.y);
                fa0[2] = add2(fa0[2], pB.x); fa0[3] = add2(fa0[3], pB.y);
            }
            if (g < 3) {
                ulonglong2 pA = ((const ulonglong2*)(s + 8))[0];
                ulonglong2 pB = ((const ulonglong2*)(s + 12))[0];
                fa1[0] = add2(fa1[0], pA.x); fa1[1] = add2(fa1[1], pA.y);
                fa1[2] = add2(fa1[2], pB.x); fa1[3] = add2(fa1[3], pB.y);
            }
            float sc = bn1_w[o16] * rsqrtf(bn1_v[o16] + EPSV);
            float bi = fmaf(b1[o16], sc, bn1_b[o16] - bn1_m[o16] * sc);
            float r0[8];
            up2(fa0[0],r0[0],r0[1]); up2(fa0[1],r0[2],r0[3]);
            up2(fa0[2],r0[4],r0[5]); up2(fa0[3],r0[6],r0[7]);
            float* dst = sm + XPA_OFF + o16 * 108 + (p0 + 1) * 12 + 1;
            #pragma unroll
            for (int q = 0; q < 8; ++q) dst[q] = fmaxf(fmaf(r0[q], sc, bi), 0.f);
            if (g < 3) {
                float r1[8];
                up2(fa1[0],r1[0],r1[1]); up2(fa1[1],r1[2],r1[3]);
                up2(fa1[2],r1[4],r1[5]); up2(fa1[3],r1[6],r1[7]);
                #pragma unroll
                for (int q = 0; q < 8; ++q) dst[12 + q] = fmaxf(fmaf(r1[q], sc, bi), 0.f);
            }
        }
    }
    __syncthreads();

    // ============ Stage G: conv2 3x3 16->1 ============
    if (t < 56) {
        int p = t >> 3, q = t & 7;
        float acc2 = b2[0];
        #pragma unroll 4
        for (int i = 0; i < 16; ++i) {
            const float* xc = sm + XPA_OFF + i * 108 + p * 12 + q;
            const float* wg = sm + W2_OFF + i * 9;
            acc2 = fmaf(wg[0], xc[0],  acc2);
            acc2 = fmaf(wg[1], xc[1],  acc2);
            acc2 = fmaf(wg[2], xc[2],  acc2);
            acc2 = fmaf(wg[3], xc[12], acc2);
            acc2 = fmaf(wg[4], xc[13], acc2);
            acc2 = fmaf(wg[5], xc[14], acc2);
            acc2 = fmaf(wg[6], xc[24], acc2);
            acc2 = fmaf(wg[7], xc[25], acc2);
            acc2 = fmaf(wg[8], xc[26], acc2);
        }
        out[(size_t)b * 56 + t] = acc2;
    }
}

extern "C" void kernel_launch(void* const* d_in, const int* in_sizes, int n_in,
                              void* d_out, int out_size) {
    const float* mg      = (const float*)d_in[0];
    const float* w_cr    = (const float*)d_in[1];
    const float* b_cr    = (const float*)d_in[2];
    const float* bnr_w   = (const float*)d_in[3];
    const float* bnr_b   = (const float*)d_in[4];
    const float* bnr_m   = (const float*)d_in[5];
    const float* bnr_v   = (const float*)d_in[6];
    const float* q_w     = (const float*)d_in[7];
    const float* q_b     = (const float*)d_in[8];
    const float* k_w     = (const float*)d_in[9];
    const float* k_b     = (const float*)d_in[10];
    const float* v_w     = (const float*)d_in[11];
    const float* v_b     = (const float*)d_in[12];
    const float* gamma   = (const float*)d_in[13];
    const float* ln_w    = (const float*)d_in[14];
    const float* ln_b    = (const float*)d_in[15];
    const float* w_res   = (const float*)d_in[16];
    const float* b_res   = (const float*)d_in[17];
    const float* bnres_w = (const float*)d_in[18];
    const float* bnres_b = (const float*)d_in[19];
    const float* bnres_m = (const float*)d_in[20];
    const float* bnres_v = (const float*)d_in[21];
    const float* w1      = (const float*)d_in[22];
    const float* b1      = (const float*)d_in[23];
    const float* bn1_w   = (const float*)d_in[24];
    const float* bn1_b   = (const float*)d_in[25];
    const float* bn1_m   = (const float*)d_in[26];
    const float* bn1_v   = (const float*)d_in[27];
    const float* w2      = (const float*)d_in[28];
    const float* b2      = (const float*)d_in[29];

    int B = in_sizes[0] / 32768;
    size_t smem_bytes = SMEM_FLOATS * sizeof(float);   // 56KB -> 4 CTAs/SM
    cudaFuncSetAttribute(occ_fused_kernel,
                         cudaFuncAttributeMaxDynamicSharedMemorySize, (int)smem_bytes);
    occ_fused_kernel<<<B, 256, smem_bytes>>>(
        mg, w_cr, b_cr, bnr_w, bnr_b, bnr_m, bnr_v,
        q_w, q_b, k_w, k_b, v_w, v_b, gamma, ln_w, ln_b,
        w_res, b_res, bnres_w, bnres_b, bnres_m, bnres_v,
        w1, b1, bn1_w, bn1_b, bn1_m, bn1_v, w2, b2,
        (float*)d_out);
}

// round 14
// speedup vs baseline: 1.3963x; 1.3963x over previous
#include <cuda_runtime.h>

#define EPSV 1e-5f
typedef unsigned long long ull;

// ---------------- shared memory layout (float offsets), 14336 floats = 56KB --
// Phase 1:
//   [0,7168)      pooled[128][56]
//     after stage B (pooled+wcrT dead): QT[4][60]@0, KT[4][60]@240,
//        VT[56][32]@480, S[56][60]@2272..5632, attnT[56][60]@5632..8992,
//        RED@8992..9024
//   [7168,11392)  wcrT as 64 c-pairs x 33 ull slots (4224 floats; dead after B)
//   [11392,12416) vTw[32][32]
//   [12416,14336) xbuf[32][60]
// Phase 2:
//   [0,3456)      xpadA[32][9][12]   (ch16+ region reused as F-merge scratch)
//   [3456,5760)   shA[32][9][8]
//   [3424,5760)   shB (aliases shA + 32-float XPA tail; halves @3424/4592)
//   [5760,9248)   xpadB 2 halves of [16][9][12], half stride 1744
//   [9248,14000)  wres half [144][33]=4752 (reused as E-merge scratch);
//                 later w1T 2x[144][17] @9248/11696
//   [14144,14288) w2
#define POOL_OFF 0
#define QT_OFF   0
#define KT_OFF   240
#define VT_OFF   480
#define S_OFF    2272
#define ATT_OFF  5632
#define RED_OFF  8992
#define WCRT_OFF 7168
#define VTW_OFF  11392
#define XBUF_OFF 12416

#define XPA_OFF  0
#define SHA_OFF  3456
#define SHB_OFF  3424
#define XPB_OFF  5760
#define WR2_OFF  9248
#define W2_OFF   14144
#define SMEM_FLOATS 14336

#define FSCR_OFF (XPA_OFF + 1728)   // F-merge scratch (dead xpadA ch16+)

// ---------------- packed f32x2 helpers ----------------
__device__ __forceinline__ ull pk2(float x, float y) {
    ull r; asm("mov.b64 %0, {%1, %2};" : "=l"(r) : "f"(x), "f"(y)); return r;
}
__device__ __forceinline__ void up2(ull v, float& x, float& y) {
    asm("mov.b64 {%0, %1}, %2;" : "=f"(x), "=f"(y) : "l"(v));
}
__device__ __forceinline__ ull fma2(ull a, ull b, ull c) {
    ull r; asm("fma.rn.f32x2 %0, %1, %2, %3;" : "=l"(r) : "l"(a), "l"(b), "l"(c)); return r;
}
__device__ __forceinline__ ull add2(ull a, ull b) {
    ull r; asm("add.rn.f32x2 %0, %1, %2;" : "=l"(r) : "l"(a), "l"(b)); return r;
}

// 8-wide GEMM step: acc[4] += w * x[0..7], x warp-uniform (broadcast LDS.128)
// REQUIREMENT: x must be 16B-aligned (float offset % 4 == 0)
__device__ __forceinline__ void g8(ull acc[4], const float* __restrict__ x, float wv) {
    ulonglong2 A = *(const ulonglong2*)(x);
    ulonglong2 B = *(const ulonglong2*)(x + 4);
    ull wp = pk2(wv, wv);
    acc[0] = fma2(wp, A.x, acc[0]); acc[1] = fma2(wp, A.y, acc[1]);
    acc[2] = fma2(wp, B.x, acc[2]); acc[3] = fma2(wp, B.y, acc[3]);
}

// one 3-tap row application: 12 FFMA2 for 8 outputs
__device__ __forceinline__ void apply9(ull acc[4], const ull* __restrict__ W,
        const ulonglong2& E01, const ulonglong2& E23, ull E4,
        const ulonglong2& O01, const ulonglong2& O23) {
    acc[0] = fma2(W[0], E01.x, acc[0]); acc[1] = fma2(W[0], E01.y, acc[1]);
    acc[2] = fma2(W[0], E23.x, acc[2]); acc[3] = fma2(W[0], E23.y, acc[3]);
    acc[0] = fma2(W[1], O01.x, acc[0]); acc[1] = fma2(W[1], O01.y, acc[1]);
    acc[2] = fma2(W[1], O23.x, acc[2]); acc[3] = fma2(W[1], O23.y, acc[3]);
    acc[0] = fma2(W[2], E01.y, acc[0]); acc[1] = fma2(W[2], E23.x, acc[1]);
    acc[2] = fma2(W[2], E23.y, acc[2]); acc[3] = fma2(W[2], E4,    acc[3]);
}

// 3x3 conv over nch channels (channel steps xstep/sstep/wstep allow parity
// splits), output rows p0 (and p0+1 if TWO). Weights loaded once per channel.
// E4 = (x8, 0) reconstructed from O23.y (x9 is always pad-zero).
template<bool TWO>
__device__ __forceinline__ void conv_pair(ull a0[4], ull a1[4],
    const float* __restrict__ xb, const float* __restrict__ sb,
    const float* __restrict__ wb, int ws, int o, int p0, int nch,
    int xstep, int sstep, int wstep) {
    #pragma unroll 1
    for (int ch = 0; ch < nch; ++ch) {
        const float* wp = wb + ch * wstep + o;
        ull W[9];
        #pragma unroll
        for (int k = 0; k < 9; ++k) { float wv = wp[k * ws]; W[k] = pk2(wv, wv); }
        const float* xrow = xb + ch * xstep + p0 * 12;
        const float* srow = sb + ch * sstep + p0 * 8;
        #pragma unroll
        for (int r = 0; r < (TWO ? 4 : 3); ++r) {
            ulonglong2 E01 = *(const ulonglong2*)(xrow + r * 12);
            ulonglong2 E23 = *(const ulonglong2*)(xrow + r * 12 + 4);
            ulonglong2 O01 = *(const ulonglong2*)(srow + r * 8);
            ulonglong2 O23 = *(const ulonglong2*)(srow + r * 8 + 4);
            ull E4 = O23.y >> 32;                 // (x8, 0)
            if (r < 3)         apply9(a0, W + 3 * r,       E01, E23, E4, O01, O23);
            if (TWO && r >= 1) apply9(a1, W + 3 * (r - 1), E01, E23, E4, O01, O23);
        }
    }
}

__global__ void __launch_bounds__(256, 4) occ_fused_kernel(
    const float* __restrict__ mg,
    const float* __restrict__ w_cr, const float* __restrict__ b_cr,
    const float* __restrict__ bnr_w, const float* __restrict__ bnr_b,
    const float* __restrict__ bnr_m, const float* __restrict__ bnr_v,
    const float* __restrict__ q_w,  const float* __restrict__ q_b,
    const float* __restrict__ k_w,  const float* __restrict__ k_b,
    const float* __restrict__ v_w,  const float* __restrict__ v_b,
    const float* __restrict__ gamma,
    const float* __restrict__ ln_w, const float* __restrict__ ln_b,
    const float* __restrict__ w_res, const float* __restrict__ b_res,
    const float* __restrict__ bnres_w, const float* __restrict__ bnres_b,
    const float* __restrict__ bnres_m, const float* __restrict__ bnres_v,
    const float* __restrict__ w1,  const float* __restrict__ b1,
    const float* __restrict__ bn1_w, const float* __restrict__ bn1_b,
    const float* __restrict__ bn1_m, const float* __restrict__ bn1_v,
    const float* __restrict__ w2,  const float* __restrict__ b2,
    float* __restrict__ out)
{
    extern __shared__ float sm[];
    const int t = threadIdx.x;
    const int b = blockIdx.x;
    const int w = t >> 5;
    const int lane = t & 31;
    float* red = sm + RED_OFF;

    // ============ Stage A: vectorized adaptive pool 16x16 -> 7x8 + weight staging =
    {
        const float* in = mg + (size_t)b * 32768;
        // 1792 groups of 4 outputs: group = (c, p, qq); qq selects cols 8qq..8qq+7
        int c = t / 14, rem = t - c * 14;
        #pragma unroll 1
        for (int k = 0; k < 7; ++k) {
            int p = rem >> 1, qq = rem & 1;
            int r0 = (0xDB96420u >> (p * 4)) & 0xF;
            bool four = (p == 3);
            const float4* bp4 = (const float4*)(in + c * 256 + qq * 8) + r0 * 4;
            float4 A0 = bp4[0], B0 = bp4[1];
            float4 A1 = bp4[4], B1 = bp4[5];
            float4 A2 = bp4[8], B2 = bp4[9];
            float s0 = A0.x + A0.y + A1.x + A1.y + A2.x + A2.y;
            float s1 = A0.z + A0.w + A1.z + A1.w + A2.z + A2.w;
            float s2 = B0.x + B0.y + B1.x + B1.y + B2.x + B2.y;
            float s3 = B0.z + B0.w + B1.z + B1.w + B2.z + B2.w;
            float scale = 0.16666667f;
            if (four) {
                float4 A3 = bp4[12], B3 = bp4[13];
                s0 += A3.x + A3.y; s1 += A3.z + A3.w;
                s2 += B3.x + B3.y; s3 += B3.z + B3.w;
                scale = 0.125f;
            }
            *(float4*)(sm + POOL_OFF + c * 56 + p * 8 + qq * 4) =
                make_float4(s0 * scale, s1 * scale, s2 * scale, s3 * scale);
            rem += 4; c += 18; if (rem >= 14) { rem -= 14; ++c; }
        }
        // wcrT as c-pairs: slot [cp][o] = (w[2cp][o], w[2cp+1][o]) ull, stride 66 fl
        #pragma unroll
        for (int k = 0; k < 4; ++k) {
            int idx = t + k * 256;            // 1024 float4 groups
            int o = idx >> 5, c4 = (idx & 31) * 4;
            float4 wv = *(const float4*)(w_cr + o * 128 + c4);
            float* dst = sm + WCRT_OFF + (c4 >> 1) * 66 + o * 2;
            *(ull*)dst        = pk2(wv.x, wv.y);
            *(ull*)(dst + 66) = pk2(wv.z, wv.w);
        }
        {   // vTw[in][o], stride 32 — coalesced LDG.128, transposed STS
            int o = t >> 3, in4 = (t & 7) * 4;
            float4 vv = *(const float4*)(v_w + o * 32 + in4);
            sm[VTW_OFF + (in4 + 0) * 32 + o] = vv.x;
            sm[VTW_OFF + (in4 + 1) * 32 + o] = vv.y;
            sm[VTW_OFF + (in4 + 2) * 32 + o] = vv.z;
            sm[VTW_OFF + (in4 + 3) * 32 + o] = vv.w;
        }
    }
    __syncthreads();

    // ============ Stage B: 1x1 128->32 + BN + ReLU. warp=p, lane=o ============
    if (w < 7) {
        ull a[4] = {0,0,0,0};
        const float* xb = sm + POOL_OFF + w * 8;
        const float* wc = sm + WCRT_OFF + lane * 2;
        #pragma unroll 4
        for (int cp = 0; cp < 64; ++cp) {
            ull wpair = *(const ull*)(wc + cp * 66);
            float w0, w1; up2(wpair, w0, w1);
            g8(a, xb + (2 * cp) * 56, w0);
            g8(a, xb + (2 * cp + 1) * 56, w1);
        }
        float sc = bnr_w[lane] * rsqrtf(bnr_v[lane] + EPSV);
        float bi = fmaf(b_cr[lane], sc, bnr_b[lane] - bnr_m[lane] * sc);
        float r[8];
        up2(a[0],r[0],r[1]); up2(a[1],r[2],r[3]); up2(a[2],r[4],r[5]); up2(a[3],r[6],r[7]);
        float* dst = sm + XBUF_OFF + lane * 60 + w * 8;
        #pragma unroll
        for (int q = 0; q < 8; ++q) dst[q] = fmaxf(fmaf(r[q], sc, bi), 0.f);
    }
    __syncthreads();

    // ============ Stage C1: v (warps 0-6), q & k (warp 7, weights via gmem) =======
    if (w < 7) {
        float bias = v_b[lane];
        ull a[4]; a[0]=a[1]=a[2]=a[3]=pk2(bias,bias);
        const float* xb = sm + XBUF_OFF + w * 8;
        const float* wv2p = sm + VTW_OFF + lane;
        #pragma unroll 4
        for (int in2 = 0; in2 < 32; ++in2)
            g8(a, xb + in2 * 60, wv2p[in2 * 32]);
        float r[8];
        up2(a[0],r[0],r[1]); up2(a[1],r[2],r[3]); up2(a[2],r[4],r[5]); up2(a[3],r[6],r[7]);
        #pragma unroll
        for (int q = 0; q < 8; ++q) sm[VT_OFF + (w * 8 + q) * 32 + lane] = r[q];
    } else if (lane < 28) {
        int d = lane / 7, p = lane - d * 7;
        const float* xb = sm + XBUF_OFF + p * 8;
        #pragma unroll
        for (int pass = 0; pass < 2; ++pass) {
            const float* W = (pass ? k_w : q_w) + d * 32;
            float bias = pass ? k_b[d] : q_b[d];
            ull a[4]; a[0]=a[1]=a[2]=a[3]=pk2(bias,bias);
            for (int in2 = 0; in2 < 32; ++in2) g8(a, xb + in2 * 60, __ldg(W + in2));
            float r[8];
            up2(a[0],r[0],r[1]); up2(a[1],r[2],r[3]); up2(a[2],r[4],r[5]); up2(a[3],r[6],r[7]);
            float* dst = sm + (pass ? KT_OFF : QT_OFF) + d * 60 + p * 8;
            #pragma unroll
            for (int q = 0; q < 8; ++q) dst[q] = r[q];
        }
    }
    __syncthreads();

    // ============ Stage C2: S[i][j] = sum_d q[d][i] k[d][j] ============
    if (w < 7) {
        int i0 = w * 8;
        #pragma unroll
        for (int seg = 0; seg < 2; ++seg) {
            int j = seg * 32 + lane;
            if (j < 56) {
                ull a[4] = {0,0,0,0};
                #pragma unroll
                for (int d = 0; d < 4; ++d)
                    g8(a, sm + QT_OFF + d * 60 + i0, sm[KT_OFF + d * 60 + j]);
                float r[8];
                up2(a[0],r[0],r[1]); up2(a[1],r[2],r[3]); up2(a[2],r[4],r[5]); up2(a[3],r[6],r[7]);
                #pragma unroll
                for (int q = 0; q < 8; ++q) sm[S_OFF + (i0 + q) * 60 + j] = r[q];
            }
        }
    }
    __syncthreads();

    // ============ softmax: 8 warps x 7 rows, shfl reductions, write attnT[j][i] ===
    {
        int i0 = w * 7;
        #pragma unroll 1
        for (int rr = 0; rr < 7; ++rr) {
            int i = i0 + rr;
            const float* row = sm + S_OFF + i * 60;
            float v0 = row[lane];
            float v1 = (lane < 24) ? row[32 + lane] : -1e30f;
            float m = fmaxf(v0, v1);
            #pragma unroll
            for (int off = 16; off; off >>= 1)
                m = fmaxf(m, __shfl_xor_sync(0xffffffffu, m, off));
            float e0 = __expf(v0 - m);
            float e1 = (lane < 24) ? __expf(v1 - m) : 0.f;
            float ssum = e0 + e1;
            #pragma unroll
            for (int off = 16; off; off >>= 1)
                ssum += __shfl_xor_sync(0xffffffffu, ssum, off);
            float inv = 1.f / ssum;
            sm[ATT_OFF + lane * 60 + i] = e0 * inv;
            if (lane < 24) sm[ATT_OFF + (32 + lane) * 60 + i] = e1 * inv;
        }
    }
    __syncthreads();

    // ============ Stage C3: out[c][i] = sum_j v[j][c]*attnT[j][i]; x += gamma*out ==
    if (w < 7) {
        int i0 = w * 8;
        ull a[4] = {0,0,0,0};
        #pragma unroll 4
        for (int j = 0; j < 56; ++j)
            g8(a, sm + ATT_OFF + j * 60 + i0, sm[VT_OFF + j * 32 + lane]);
        float r[8];
        up2(a[0],r[0],r[1]); up2(a[1],r[2],r[3]); up2(a[2],r[4],r[5]); up2(a[3],r[6],r[7]);
        float g = gamma[0];
        float* xr = sm + XBUF_OFF + lane * 60 + i0;
        #pragma unroll
        for (int q = 0; q < 8; ++q) xr[q] = fmaf(g, r[q], xr[q]);
    }
    __syncthreads();

    // ============ Stage D: LayerNorm over 1792 ============
    float vals[7];
    {
        float s1 = 0.f, s2 = 0.f;
        int c = t / 56, s = t - c * 56;
        #pragma unroll
        for (int k = 0; k < 7; ++k) {
            float x = sm[XBUF_OFF + c * 60 + s];
            vals[k] = x; s1 += x; s2 = fmaf(x, x, s2);
            s += 32; c += 4; if (s >= 56) { s -= 56; ++c; }
        }
        #pragma unroll
        for (int off = 16; off; off >>= 1) {
            s1 += __shfl_xor_sync(0xffffffffu, s1, off);
            s2 += __shfl_xor_sync(0xffffffffu, s2, off);
        }
        if (lane == 0) { red[w] = s1; red[8 + w] = s2; }
        __syncthreads();
        if (t == 0) {
            float S1 = 0.f, S2 = 0.f;
            for (int k = 0; k < 8; ++k) { S1 += red[k]; S2 += red[8 + k]; }
            float mu = S1 * (1.f / 1792.f);
            float var = S2 * (1.f / 1792.f) - mu * mu;
            red[16] = mu; red[17] = rsqrtf(var + EPSV);
        }
        __syncthreads();
        float mu = red[16], inv = red[17];
        #pragma unroll
        for (int k = 0; k < 7; ++k) {
            int v = t + k * 256;
            vals[k] = (vals[k] - mu) * inv * ln_w[v] + ln_b[v];
        }
    }
    __syncthreads();   // all phase-1 activation reads done

    // zero phase-2 activation region [0,9248) + stage w_res half 1
    {
        float4 z4 = make_float4(0.f, 0.f, 0.f, 0.f);
        float4* z = (float4*)sm;
        for (int idx = t; idx < 2312; idx += 256) z[idx] = z4;
        for (int idx = t; idx < 4608; idx += 256) {
            int o = idx / 144, r = idx - o * 144;
            sm[WR2_OFF + r * 33 + o] = w_res[o * 288 + r];
        }
    }
    __syncthreads();
    {
        int c = t / 56, s = t - c * 56;
        #pragma unroll
        for (int k = 0; k < 7; ++k) {   // scatter LN output into xpadA + shifted shA
            int p = s >> 3, q = s & 7;
            sm[XPA_OFF + c * 108 + (p + 1) * 12 + (q + 1)] = vals[k];
            sm[SHA_OFF + c * 72 + (p + 1) * 8 + q] = vals[k];
            s += 32; c += 4; if (s >= 56) { s -= 56; ++c; }
        }
    }
    __syncthreads();

    // ============ Stage E: 3x3 conv 32->32, 8 warps: row-pair (g) x parity (par) ==
    const int g   = w & 3;
    const int par = w >> 2;
    const int p0  = (g < 3) ? 2 * g : 6;
    ull ea0[4] = {0,0,0,0}, ea1[4] = {0,0,0,0};
    {   // half 1: input channels par, par+2, ..., par+14
        const float* xb = sm + XPA_OFF + par * 108;
        const float* sb = sm + SHA_OFF + par * 72;
        const float* wb = sm + WR2_OFF + par * 297;   // par*9*33
        if (g < 3) conv_pair<true >(ea0, ea1, xb, sb, wb, 33, lane, p0, 8, 216, 144, 594);
        else       conv_pair<false>(ea0, ea1, xb, sb, wb, 33, lane, 6,  8, 216, 144, 594);
    }
    __syncthreads();
    for (int idx = t; idx < 4608; idx += 256) {    // stage w_res half 2
        int o = idx / 144, r = idx - o * 144;
        sm[WR2_OFF + r * 33 + o] = w_res[o * 288 + 144 + r];
    }
    __syncthreads();
    {   // half 2: input channels 16+par, 16+par+2, ...
        const float* xb = sm + XPA_OFF + (16 + par) * 108;
        const float* sb = sm + SHA_OFF + (16 + par) * 72;
        const float* wb = sm + WR2_OFF + par * 297;
        if (g < 3) conv_pair<true >(ea0, ea1, xb, sb, wb, 33, lane, p0, 8, 216, 144, 594);
        else       conv_pair<false>(ea0, ea1, xb, sb, wb, 33, lane, 6,  8, 216, 144, 594);
    }
    __syncthreads();   // conv reads of WR2 / shA done

    // E-merge phase 1: warps 4-7 park partials in dead WR2; warps 0-3 stage w2
    if (w >= 4) {
        float* s = sm + WR2_OFF + g * 640 + lane * 20;
        ((ulonglong2*)s)[0]       = make_ulonglong2(ea0[0], ea0[1]);
        ((ulonglong2*)(s + 4))[0] = make_ulonglong2(ea0[2], ea0[3]);
        if (g < 3) {
            ((ulonglong2*)(s + 8))[0]  = make_ulonglong2(ea1[0], ea1[1]);
            ((ulonglong2*)(s + 12))[0] = make_ulonglong2(ea1[2], ea1[3]);
        }
    } else {
        for (int idx = t; idx < 144; idx += 128) sm[W2_OFF + idx] = w2[idx];
    }
    __syncthreads();

    // E-merge phase 2: warps 0-3 add partner partials + BN + ReLU + residual -> regs
    // (NO shB/xpadB writes here: shB overlaps xpadA tail read as residual by g=3.
    //  All residual reads complete before the barrier below.)
    float er0[8], er1[8];
    if (w < 4) {
        const float* s = sm + WR2_OFF + g * 640 + lane * 20;
        {
            ulonglong2 pA = ((const ulonglong2*)s)[0];
            ulonglong2 pB = ((const ulonglong2*)(s + 4))[0];
            ea0[0] = add2(ea0[0], pA.x); ea0[1] = add2(ea0[1], pA.y);
            ea0[2] = add2(ea0[2], pB.x); ea0[3] = add2(ea0[3], pB.y);
        }
        if (g < 3) {
            ulonglong2 pA = ((const ulonglong2*)(s + 8))[0];
            ulonglong2 pB = ((const ulonglong2*)(s + 12))[0];
            ea1[0] = add2(ea1[0], pA.x); ea1[1] = add2(ea1[1], pA.y);
            ea1[2] = add2(ea1[2], pB.x); ea1[3] = add2(ea1[3], pB.y);
        }
        float sc = bnres_w[lane] * rsqrtf(bnres_v[lane] + EPSV);
        float bi = fmaf(b_res[lane], sc, bnres_b[lane] - bnres_m[lane] * sc);
        const float* rs0 = sm + XPA_OFF + lane * 108 + (p0 + 1) * 12 + 1;
        float r0[8];
        up2(ea0[0],r0[0],r0[1]); up2(ea0[1],r0[2],r0[3]);
        up2(ea0[2],r0[4],r0[5]); up2(ea0[3],r0[6],r0[7]);
        #pragma unroll
        for (int q = 0; q < 8; ++q) er0[q] = fmaxf(fmaf(r0[q], sc, bi), 0.f) + rs0[q];
        if (g < 3) {
            float r1[8];
            up2(ea1[0],r1[0],r1[1]); up2(ea1[1],r1[2],r1[3]);
            up2(ea1[2],r1[4],r1[5]); up2(ea1[3],r1[6],r1[7]);
            const float* rs1 = rs0 + 12;
            #pragma unroll
            for (int q = 0; q < 8; ++q) er1[q] = fmaxf(fmaf(r1[q], sc, bi), 0.f) + rs1[q];
        }
    }
    __syncthreads();   // all residual/shA reads + scratch reads done

    // write stage-E rows into xpadB/shB, zero shB pad rows, stage w1T concurrently
    if (w < 4) {
        int hoff = (lane >> 4) * 16;
        float* db0 = sm + XPB_OFF + lane * 108 + hoff + (p0 + 1) * 12 + 1;
        float* sb0 = sm + SHB_OFF + lane * 72 + hoff + (p0 + 1) * 8;
        #pragma unroll
        for (int q = 0; q < 8; ++q) { db0[q] = er0[q]; sb0[q] = er0[q]; }
        if (g < 3) {
            #pragma unroll
            for (int q = 0; q < 8; ++q) { db0[12 + q] = er1[q]; sb0[8 + q] = er1[q]; }
        }
    } else {
        for (int idx = t - 128; idx < 512; idx += 128) {   // zero shB pad rows 0 & 8
            int ch = idx >> 4, rem = idx & 15;
            int rowoff = (rem & 8) ? 64 : 0, q = rem & 7;
            sm[SHB_OFF + ch * 72 + (ch >> 4) * 16 + rowoff + q] = 0.f;
        }
    }
    for (int idx = t; idx < 4608; idx += 256) {    // w1T two halves, stride 17
        int o = idx / 288, rr = idx - o * 288;
        int half = (rr >= 144) ? 1 : 0, rp = rr - half * 144;
        sm[WR2_OFF + half * 2448 + rp * 17 + o] = w1[idx];
    }
    __syncthreads();

    // ============ Stage F: 3x3 conv 32->16, 8 warps: rows x parity, lane halves ===
    {
        int o16 = lane & 15, half = lane >> 4;
        const float* xb = sm + XPB_OFF + half * 1744 + par * 108;
        const float* sb = sm + SHB_OFF + half * 1168 + par * 72;
        const float* wb = sm + WR2_OFF + half * 2448 + par * 153;  // par*9*17
        ull fa0[4] = {0,0,0,0}, fa1[4] = {0,0,0,0};
        if (g < 3) conv_pair<true >(fa0, fa1, xb, sb, wb, 17, o16, p0, 8, 216, 144, 306);
        else       conv_pair<false>(fa0, fa1, xb, sb, wb, 17, o16, 6,  8, 216, 144, 306);
        #pragma unroll
        for (int m = 0; m < 4; ++m) {
            fa0[m] = add2(fa0[m], __shfl_xor_sync(0xffffffffu, fa0[m], 16));
            fa1[m] = add2(fa1[m], __shfl_xor_sync(0xffffffffu, fa1[m], 16));
        }
        if (w >= 4 && lane < 16) {   // park parity-1 partials in dead xpadA ch16+
            float* s = sm + FSCR_OFF + g * 320 + lane * 20;
            ((ulonglong2*)s)[0]       = make_ulonglong2(fa0[0], fa0[1]);
            ((ulonglong2*)(s + 4))[0] = make_ulonglong2(fa0[2], fa0[3]);
            if (g < 3) {
                ((ulonglong2*)(s + 8))[0]  = make_ulonglong2(fa1[0], fa1[1]);
                ((ulonglong2*)(s + 12))[0] = make_ulonglong2(fa1[2], fa1[3]);
            }
        }
        __syncthreads();
        if (w < 4 && lane < 16) {
            const float* s = sm + FSCR_OFF + g * 320 + lane * 20;
            {
                ulonglong2 pA = ((const ulonglong2*)s)[0];
                ulonglong2 pB = ((const ulonglong2*)(s + 4))[0];
                fa0[0] = add2(fa0[0], pA.x); fa0[1] = add2(fa0[1], pA.y);
                fa0[2] = add2(fa0[2], pB.x); fa0[3] = add2(fa0[3], pB.y);
            }
            if (g < 3) {
                ulonglong2 pA = ((const ulonglong2*)(s + 8))[0];
                ulonglong2 pB = ((const ulonglong2*)(s + 12))[0];
                fa1[0] = add2(fa1[0], pA.x); fa1[1] = add2(fa1[1], pA.y);
                fa1[2] = add2(fa1[2], pB.x); fa1[3] = add2(fa1[3], pB.y);
            }
            float sc = bn1_w[o16] * rsqrtf(bn1_v[o16] + EPSV);
            float bi = fmaf(b1[o16], sc, bn1_b[o16] - bn1_m[o16] * sc);
            float r0[8];
            up2(fa0[0],r0[0],r0[1]); up2(fa0[1],r0[2],r0[3]);
            up2(fa0[2],r0[4],r0[5]); up2(fa0[3],r0[6],r0[7]);
            float* dst = sm + XPA_OFF + o16 * 108 + (p0 + 1) * 12 + 1;
            #pragma unroll
            for (int q = 0; q < 8; ++q) dst[q] = fmaxf(fmaf(r0[q], sc, bi), 0.f);
            if (g < 3) {
                float r1[8];
                up2(fa1[0],r1[0],r1[1]); up2(fa1[1],r1[2],r1[3]);
                up2(fa1[2],r1[4],r1[5]); up2(fa1[3],r1[6],r1[7]);
                #pragma unroll
                for (int q = 0; q < 8; ++q) dst[12 + q] = fmaxf(fmaf(r1[q], sc, bi), 0.f);
            }
        }
    }
    __syncthreads();

    // ============ Stage G: conv2 3x3 16->1 ============
    if (t < 56) {
        int p = t >> 3, q = t & 7;
        float acc2 = b2[0];
        #pragma unroll 4
        for (int i = 0; i < 16; ++i) {
            const float* xc = sm + XPA_OFF + i * 108 + p * 12 + q;
            const float* wg = sm + W2_OFF + i * 9;
            acc2 = fmaf(wg[0], xc[0],  acc2);
            acc2 = fmaf(wg[1], xc[1],  acc2);
            acc2 = fmaf(wg[2], xc[2],  acc2);
            acc2 = fmaf(wg[3], xc[12], acc2);
            acc2 = fmaf(wg[4], xc[13], acc2);
            acc2 = fmaf(wg[5], xc[14], acc2);
            acc2 = fmaf(wg[6], xc[24], acc2);
            acc2 = fmaf(wg[7], xc[25], acc2);
            acc2 = fmaf(wg[8], xc[26], acc2);
        }
        out[(size_t)b * 56 + t] = acc2;
    }
}

extern "C" void kernel_launch(void* const* d_in, const int* in_sizes, int n_in,
                              void* d_out, int out_size) {
    const float* mg      = (const float*)d_in[0];
    const float* w_cr    = (const float*)d_in[1];
    const float* b_cr    = (const float*)d_in[2];
    const float* bnr_w   = (const float*)d_in[3];
    const float* bnr_b   = (const float*)d_in[4];
    const float* bnr_m   = (const float*)d_in[5];
    const float* bnr_v   = (const float*)d_in[6];
    const float* q_w     = (const float*)d_in[7];
    const float* q_b     = (const float*)d_in[8];
    const float* k_w     = (const float*)d_in[9];
    const float* k_b     = (const float*)d_in[10];
    const float* v_w     = (const float*)d_in[11];
    const float* v_b     = (const float*)d_in[12];
    const float* gamma   = (const float*)d_in[13];
    const float* ln_w    = (const float*)d_in[14];
    const float* ln_b    = (const float*)d_in[15];
    const float* w_res   = (const float*)d_in[16];
    const float* b_res   = (const float*)d_in[17];
    const float* bnres_w = (const float*)d_in[18];
    const float* bnres_b = (const float*)d_in[19];
    const float* bnres_m = (const float*)d_in[20];
    const float* bnres_v = (const float*)d_in[21];
    const float* w1      = (const float*)d_in[22];
    const float* b1      = (const float*)d_in[23];
    const float* bn1_w   = (const float*)d_in[24];
    const float* bn1_b   = (const float*)d_in[25];
    const float* bn1_m   = (const float*)d_in[26];
    const float* bn1_v   = (const float*)d_in[27];
    const float* w2      = (const float*)d_in[28];
    const float* b2      = (const float*)d_in[29];

    int B = in_sizes[0] / 32768;
    size_t smem_bytes = SMEM_FLOATS * sizeof(float);   // 56KB -> 4 CTAs/SM
    cudaFuncSetAttribute(occ_fused_kernel,
                         cudaFuncAttributeMaxDynamicSharedMemorySize, (int)smem_bytes);
    occ_fused_kernel<<<B, 256, smem_bytes>>>(
        mg, w_cr, b_cr, bnr_w, bnr_b, bnr_m, bnr_v,
        q_w, q_b, k_w, k_b, v_w, v_b, gamma, ln_w, ln_b,
        w_res, b_res, bnres_w, bnres_b, bnres_m, bnres_v,
        w1, b1, bn1_w, bn1_b, bn1_m, bn1_v, w2, b2,
        (float*)d_out);
}

// round 15
// speedup vs baseline: 1.4126x; 1.0117x over previous
#include <cuda_runtime.h>

#define EPSV 1e-5f
typedef unsigned long long ull;

// ---------------- shared memory layout (float offsets), 14336 floats = 56KB --
// Phase 1:
//   [0,7168)      pooled[128][56]
//     after stage B (pooled+wcrT dead): QT[4][60]@0, KT[4][60]@240,
//        VT[56][32]@480, S[56][60]@2272..5632, attnT[56][60]@5632..8992,
//        RED@8992..9024
//   [7168,11392)  wcrT as 64 c-pairs x 33 ull slots (4224 floats; dead after B)
//   [11392,12416) vTw[32][32]
//   [12416,14336) xbuf[32][60]
// Phase 2:
//   [0,3456)      xpadA[32][9][12]   (ch16+ region reused as F-merge scratch)
//   [3456,5760)   shA[32][9][8]
//   [3424,5760)   shB (aliases shA + 32-float XPA tail; halves @3424/4592)
//   [5760,9248)   xpadB 2 halves of [16][9][12], half stride 1744
//   [9248,14000)  wres half [144][33]=4752 (reused as E-merge scratch);
//                 later w1T 2x[144][17] @9248/11696
//   [14144,14288) w2
#define POOL_OFF 0
#define QT_OFF   0
#define KT_OFF   240
#define VT_OFF   480
#define S_OFF    2272
#define ATT_OFF  5632
#define RED_OFF  8992
#define WCRT_OFF 7168
#define VTW_OFF  11392
#define XBUF_OFF 12416

#define XPA_OFF  0
#define SHA_OFF  3456
#define SHB_OFF  3424
#define XPB_OFF  5760
#define WR2_OFF  9248
#define W2_OFF   14144
#define SMEM_FLOATS 14336

#define FSCR_OFF (XPA_OFF + 1728)   // F-merge scratch (dead xpadA ch16+)

// ---------------- packed f32x2 helpers ----------------
__device__ __forceinline__ ull pk2(float x, float y) {
    ull r; asm("mov.b64 %0, {%1, %2};" : "=l"(r) : "f"(x), "f"(y)); return r;
}
__device__ __forceinline__ void up2(ull v, float& x, float& y) {
    asm("mov.b64 {%0, %1}, %2;" : "=f"(x), "=f"(y) : "l"(v));
}
__device__ __forceinline__ ull fma2(ull a, ull b, ull c) {
    ull r; asm("fma.rn.f32x2 %0, %1, %2, %3;" : "=l"(r) : "l"(a), "l"(b), "l"(c)); return r;
}
__device__ __forceinline__ ull add2(ull a, ull b) {
    ull r; asm("add.rn.f32x2 %0, %1, %2;" : "=l"(r) : "l"(a), "l"(b)); return r;
}

// 8-wide GEMM step: acc[4] += w * x[0..7], x warp-uniform (broadcast LDS.128)
// REQUIREMENT: x must be 16B-aligned (float offset % 4 == 0)
__device__ __forceinline__ void g8(ull acc[4], const float* __restrict__ x, float wv) {
    ulonglong2 A = *(const ulonglong2*)(x);
    ulonglong2 B = *(const ulonglong2*)(x + 4);
    ull wp = pk2(wv, wv);
    acc[0] = fma2(wp, A.x, acc[0]); acc[1] = fma2(wp, A.y, acc[1]);
    acc[2] = fma2(wp, B.x, acc[2]); acc[3] = fma2(wp, B.y, acc[3]);
}

// one 3-tap row application: 12 FFMA2 for 8 outputs
__device__ __forceinline__ void apply9(ull acc[4], const ull* __restrict__ W,
        const ulonglong2& E01, const ulonglong2& E23, ull E4,
        const ulonglong2& O01, const ulonglong2& O23) {
    acc[0] = fma2(W[0], E01.x, acc[0]); acc[1] = fma2(W[0], E01.y, acc[1]);
    acc[2] = fma2(W[0], E23.x, acc[2]); acc[3] = fma2(W[0], E23.y, acc[3]);
    acc[0] = fma2(W[1], O01.x, acc[0]); acc[1] = fma2(W[1], O01.y, acc[1]);
    acc[2] = fma2(W[1], O23.x, acc[2]); acc[3] = fma2(W[1], O23.y, acc[3]);
    acc[0] = fma2(W[2], E01.y, acc[0]); acc[1] = fma2(W[2], E23.x, acc[1]);
    acc[2] = fma2(W[2], E23.y, acc[2]); acc[3] = fma2(W[2], E4,    acc[3]);
}

// 3x3 conv over nch channels (channel steps xstep/sstep/wstep allow parity
// splits), output rows p0 (and p0+1 if TWO). Weights loaded once per channel.
// E4 = (x8, 0) reconstructed from O23.y (x9 is always pad-zero).
template<bool TWO>
__device__ __forceinline__ void conv_pair(ull a0[4], ull a1[4],
    const float* __restrict__ xb, const float* __restrict__ sb,
    const float* __restrict__ wb, int ws, int o, int p0, int nch,
    int xstep, int sstep, int wstep) {
    #pragma unroll 1
    for (int ch = 0; ch < nch; ++ch) {
        const float* wp = wb + ch * wstep + o;
        ull W[9];
        #pragma unroll
        for (int k = 0; k < 9; ++k) { float wv = wp[k * ws]; W[k] = pk2(wv, wv); }
        const float* xrow = xb + ch * xstep + p0 * 12;
        const float* srow = sb + ch * sstep + p0 * 8;
        #pragma unroll
        for (int r = 0; r < (TWO ? 4 : 3); ++r) {
            ulonglong2 E01 = *(const ulonglong2*)(xrow + r * 12);
            ulonglong2 E23 = *(const ulonglong2*)(xrow + r * 12 + 4);
            ulonglong2 O01 = *(const ulonglong2*)(srow + r * 8);
            ulonglong2 O23 = *(const ulonglong2*)(srow + r * 8 + 4);
            ull E4 = O23.y >> 32;                 // (x8, 0)
            if (r < 3)         apply9(a0, W + 3 * r,       E01, E23, E4, O01, O23);
            if (TWO && r >= 1) apply9(a1, W + 3 * (r - 1), E01, E23, E4, O01, O23);
        }
    }
}

__global__ void __launch_bounds__(256, 4) occ_fused_kernel(
    const float* __restrict__ mg,
    const float* __restrict__ w_cr, const float* __restrict__ b_cr,
    const float* __restrict__ bnr_w, const float* __restrict__ bnr_b,
    const float* __restrict__ bnr_m, const float* __restrict__ bnr_v,
    const float* __restrict__ q_w,  const float* __restrict__ q_b,
    const float* __restrict__ k_w,  const float* __restrict__ k_b,
    const float* __restrict__ v_w,  const float* __restrict__ v_b,
    const float* __restrict__ gamma,
    const float* __restrict__ ln_w, const float* __restrict__ ln_b,
    const float* __restrict__ w_res, const float* __restrict__ b_res,
    const float* __restrict__ bnres_w, const float* __restrict__ bnres_b,
    const float* __restrict__ bnres_m, const float* __restrict__ bnres_v,
    const float* __restrict__ w1,  const float* __restrict__ b1,
    const float* __restrict__ bn1_w, const float* __restrict__ bn1_b,
    const float* __restrict__ bn1_m, const float* __restrict__ bn1_v,
    const float* __restrict__ w2,  const float* __restrict__ b2,
    float* __restrict__ out)
{
    extern __shared__ float sm[];
    const int t = threadIdx.x;
    const int b = blockIdx.x;
    const int w = t >> 5;
    const int lane = t & 31;
    float* red = sm + RED_OFF;

    // ============ Stage A: coalesced shuffle-pooling 16x16 -> 7x8 + weights =======
    // Warp = 16 channels. Per channel: 2 coalesced LDG.128 (lane = float4 position:
    // row = lane>>2 (+8 for second load), colgroup cg = lane&3). Column-pool in
    // regs, row-bin sums via shfl_down (A3 = S+D4+D8 covers 3-row bins; p=3 is
    // P2_0[row6]+P2_1[row8]), gather via shfl.idx to lanes (p,cg), STS.64.
    {
        const float* in = mg + (size_t)b * 32768;
        const int cg = lane & 3;
        const int pp = lane >> 2;                           // output p (lanes <28)
        const int sA = cg + pp * 8;                         // rows 0,2,4 for p=0,1,2
        const int sB = cg + (pp - 4) * 8 + 4;               // rows 9,11,13 for p=4,5,6
        const float scale = (pp == 3) ? 0.125f : 0.16666667f;
        #pragma unroll 1
        for (int i = 0; i < 16; ++i) {
            int c = w * 16 + i;
            const float4* base = (const float4*)(in + c * 256);
            float4 v0 = base[lane];
            float4 v1 = base[lane + 32];
            float a0 = v0.x + v0.y, b0 = v0.z + v0.w;       // row lane>>2
            float a1 = v1.x + v1.y, b1 = v1.z + v1.w;       // row 8+(lane>>2)
            float a0d4 = __shfl_down_sync(0xffffffffu, a0, 4);
            float a0d8 = __shfl_down_sync(0xffffffffu, a0, 8);
            float b0d4 = __shfl_down_sync(0xffffffffu, b0, 4);
            float b0d8 = __shfl_down_sync(0xffffffffu, b0, 8);
            float a1d4 = __shfl_down_sync(0xffffffffu, a1, 4);
            float a1d8 = __shfl_down_sync(0xffffffffu, a1, 8);
            float b1d4 = __shfl_down_sync(0xffffffffu, b1, 4);
            float b1d8 = __shfl_down_sync(0xffffffffu, b1, 8);
            float P2a0 = a0 + a0d4,  P2b0 = b0 + b0d4;
            float P2a1 = a1 + a1d4,  P2b1 = b1 + b1d4;
            float A3a0 = P2a0 + a0d8, A3b0 = P2b0 + b0d8;
            float A3a1 = P2a1 + a1d8, A3b1 = P2b1 + b1d8;
            // gathers (all lanes participate; results used by lanes <28)
            float gAa = __shfl_sync(0xffffffffu, A3a0, sA);
            float gAb = __shfl_sync(0xffffffffu, A3b0, sA);
            float gBa = __shfl_sync(0xffffffffu, A3a1, sB);
            float gBb = __shfl_sync(0xffffffffu, A3b1, sB);
            float gP0a = __shfl_sync(0xffffffffu, P2a0, cg + 24);
            float gP0b = __shfl_sync(0xffffffffu, P2b0, cg + 24);
            float gP1a = __shfl_sync(0xffffffffu, P2a1, cg);
            float gP1b = __shfl_sync(0xffffffffu, P2b1, cg);
            if (lane < 28) {
                float ra = (pp < 3) ? gAa : (pp == 3) ? (gP0a + gP1a) : gBa;
                float rb = (pp < 3) ? gAb : (pp == 3) ? (gP0b + gP1b) : gBb;
                *(float2*)(sm + POOL_OFF + c * 56 + lane * 2) =
                    make_float2(ra * scale, rb * scale);
            }
        }
        // wcrT as c-pairs: slot [cp][o] = (w[2cp][o], w[2cp+1][o]) ull, stride 66 fl
        #pragma unroll
        for (int k = 0; k < 4; ++k) {
            int idx = t + k * 256;            // 1024 float4 groups
            int o = idx >> 5, c4 = (idx & 31) * 4;
            float4 wv = *(const float4*)(w_cr + o * 128 + c4);
            float* dst = sm + WCRT_OFF + (c4 >> 1) * 66 + o * 2;
            *(ull*)dst        = pk2(wv.x, wv.y);
            *(ull*)(dst + 66) = pk2(wv.z, wv.w);
        }
        {   // vTw[in][o], stride 32 — coalesced LDG.128, transposed STS
            int o = t >> 3, in4 = (t & 7) * 4;
            float4 vv = *(const float4*)(v_w + o * 32 + in4);
            sm[VTW_OFF + (in4 + 0) * 32 + o] = vv.x;
            sm[VTW_OFF + (in4 + 1) * 32 + o] = vv.y;
            sm[VTW_OFF + (in4 + 2) * 32 + o] = vv.z;
            sm[VTW_OFF + (in4 + 3) * 32 + o] = vv.w;
        }
    }
    __syncthreads();

    // ============ Stage B: 1x1 128->32 + BN + ReLU. warp=p, lane=o ============
    if (w < 7) {
        ull a[4] = {0,0,0,0};
        const float* xb = sm + POOL_OFF + w * 8;
        const float* wc = sm + WCRT_OFF + lane * 2;
        #pragma unroll 4
        for (int cp = 0; cp < 64; ++cp) {
            ull wpair = *(const ull*)(wc + cp * 66);
            float w0, w1; up2(wpair, w0, w1);
            g8(a, xb + (2 * cp) * 56, w0);
            g8(a, xb + (2 * cp + 1) * 56, w1);
        }
        float sc = bnr_w[lane] * rsqrtf(bnr_v[lane] + EPSV);
        float bi = fmaf(b_cr[lane], sc, bnr_b[lane] - bnr_m[lane] * sc);
        float r[8];
        up2(a[0],r[0],r[1]); up2(a[1],r[2],r[3]); up2(a[2],r[4],r[5]); up2(a[3],r[6],r[7]);
        float* dst = sm + XBUF_OFF + lane * 60 + w * 8;
        #pragma unroll
        for (int q = 0; q < 8; ++q) dst[q] = fmaxf(fmaf(r[q], sc, bi), 0.f);
    }
    __syncthreads();

    // ============ Stage C1: v (warps 0-6), q & k (warp 7, weights via gmem) =======
    if (w < 7) {
        float bias = v_b[lane];
        ull a[4]; a[0]=a[1]=a[2]=a[3]=pk2(bias,bias);
        const float* xb = sm + XBUF_OFF + w * 8;
        const float* wv2p = sm + VTW_OFF + lane;
        #pragma unroll 4
        for (int in2 = 0; in2 < 32; ++in2)
            g8(a, xb + in2 * 60, wv2p[in2 * 32]);
        float r[8];
        up2(a[0],r[0],r[1]); up2(a[1],r[2],r[3]); up2(a[2],r[4],r[5]); up2(a[3],r[6],r[7]);
        #pragma unroll
        for (int q = 0; q < 8; ++q) sm[VT_OFF + (w * 8 + q) * 32 + lane] = r[q];
    } else if (lane < 28) {
        int d = lane / 7, p = lane - d * 7;
        const float* xb = sm + XBUF_OFF + p * 8;
        #pragma unroll
        for (int pass = 0; pass < 2; ++pass) {
            const float* W = (pass ? k_w : q_w) + d * 32;
            float bias = pass ? k_b[d] : q_b[d];
            ull a[4]; a[0]=a[1]=a[2]=a[3]=pk2(bias,bias);
            for (int in2 = 0; in2 < 32; ++in2) g8(a, xb + in2 * 60, __ldg(W + in2));
            float r[8];
            up2(a[0],r[0],r[1]); up2(a[1],r[2],r[3]); up2(a[2],r[4],r[5]); up2(a[3],r[6],r[7]);
            float* dst = sm + (pass ? KT_OFF : QT_OFF) + d * 60 + p * 8;
            #pragma unroll
            for (int q = 0; q < 8; ++q) dst[q] = r[q];
        }
    }
    __syncthreads();

    // ============ Stage C2: S[i][j] = sum_d q[d][i] k[d][j] ============
    if (w < 7) {
        int i0 = w * 8;
        #pragma unroll
        for (int seg = 0; seg < 2; ++seg) {
            int j = seg * 32 + lane;
            if (j < 56) {
                ull a[4] = {0,0,0,0};
                #pragma unroll
                for (int d = 0; d < 4; ++d)
                    g8(a, sm + QT_OFF + d * 60 + i0, sm[KT_OFF + d * 60 + j]);
                float r[8];
                up2(a[0],r[0],r[1]); up2(a[1],r[2],r[3]); up2(a[2],r[4],r[5]); up2(a[3],r[6],r[7]);
                #pragma unroll
                for (int q = 0; q < 8; ++q) sm[S_OFF + (i0 + q) * 60 + j] = r[q];
            }
        }
    }
    __syncthreads();

    // ============ softmax: 8 warps x 7 rows, shfl reductions, write attnT[j][i] ===
    {
        int i0 = w * 7;
        #pragma unroll 1
        for (int rr = 0; rr < 7; ++rr) {
            int i = i0 + rr;
            const float* row = sm + S_OFF + i * 60;
            float v0 = row[lane];
            float v1 = (lane < 24) ? row[32 + lane] : -1e30f;
            float m = fmaxf(v0, v1);
            #pragma unroll
            for (int off = 16; off; off >>= 1)
                m = fmaxf(m, __shfl_xor_sync(0xffffffffu, m, off));
            float e0 = __expf(v0 - m);
            float e1 = (lane < 24) ? __expf(v1 - m) : 0.f;
            float ssum = e0 + e1;
            #pragma unroll
            for (int off = 16; off; off >>= 1)
                ssum += __shfl_xor_sync(0xffffffffu, ssum, off);
            float inv = 1.f / ssum;
            sm[ATT_OFF + lane * 60 + i] = e0 * inv;
            if (lane < 24) sm[ATT_OFF + (32 + lane) * 60 + i] = e1 * inv;
        }
    }
    __syncthreads();

    // ============ Stage C3: out[c][i] = sum_j v[j][c]*attnT[j][i]; x += gamma*out ==
    if (w < 7) {
        int i0 = w * 8;
        ull a[4] = {0,0,0,0};
        #pragma unroll 4
        for (int j = 0; j < 56; ++j)
            g8(a, sm + ATT_OFF + j * 60 + i0, sm[VT_OFF + j * 32 + lane]);
        float r[8];
        up2(a[0],r[0],r[1]); up2(a[1],r[2],r[3]); up2(a[2],r[4],r[5]); up2(a[3],r[6],r[7]);
        float g = gamma[0];
        float* xr = sm + XBUF_OFF + lane * 60 + i0;
        #pragma unroll
        for (int q = 0; q < 8; ++q) xr[q] = fmaf(g, r[q], xr[q]);
    }
    __syncthreads();

    // ============ Stage D: LayerNorm over 1792 ============
    float vals[7];
    {
        float s1 = 0.f, s2 = 0.f;
        int c = t / 56, s = t - c * 56;
        #pragma unroll
        for (int k = 0; k < 7; ++k) {
            float x = sm[XBUF_OFF + c * 60 + s];
            vals[k] = x; s1 += x; s2 = fmaf(x, x, s2);
            s += 32; c += 4; if (s >= 56) { s -= 56; ++c; }
        }
        #pragma unroll
        for (int off = 16; off; off >>= 1) {
            s1 += __shfl_xor_sync(0xffffffffu, s1, off);
            s2 += __shfl_xor_sync(0xffffffffu, s2, off);
        }
        if (lane == 0) { red[w] = s1; red[8 + w] = s2; }
        __syncthreads();
        if (t == 0) {
            float S1 = 0.f, S2 = 0.f;
            for (int k = 0; k < 8; ++k) { S1 += red[k]; S2 += red[8 + k]; }
            float mu = S1 * (1.f / 1792.f);
            float var = S2 * (1.f / 1792.f) - mu * mu;
            red[16] = mu; red[17] = rsqrtf(var + EPSV);
        }
        __syncthreads();
        float mu = red[16], inv = red[17];
        #pragma unroll
        for (int k = 0; k < 7; ++k) {
            int v = t + k * 256;
            vals[k] = (vals[k] - mu) * inv * ln_w[v] + ln_b[v];
        }
    }
    __syncthreads();   // all phase-1 activation reads done

    // zero phase-2 activation region [0,9248) + stage w_res half 1
    {
        float4 z4 = make_float4(0.f, 0.f, 0.f, 0.f);
        float4* z = (float4*)sm;
        for (int idx = t; idx < 2312; idx += 256) z[idx] = z4;
        for (int idx = t; idx < 4608; idx += 256) {
            int o = idx / 144, r = idx - o * 144;
            sm[WR2_OFF + r * 33 + o] = w_res[o * 288 + r];
        }
    }
    __syncthreads();
    {
        int c = t / 56, s = t - c * 56;
        #pragma unroll
        for (int k = 0; k < 7; ++k) {   // scatter LN output into xpadA + shifted shA
            int p = s >> 3, q = s & 7;
            sm[XPA_OFF + c * 108 + (p + 1) * 12 + (q + 1)] = vals[k];
            sm[SHA_OFF + c * 72 + (p + 1) * 8 + q] = vals[k];
            s += 32; c += 4; if (s >= 56) { s -= 56; ++c; }
        }
    }
    __syncthreads();

    // ============ Stage E: 3x3 conv 32->32, 8 warps: row-pair (g) x parity (par) ==
    const int g   = w & 3;
    const int par = w >> 2;
    const int p0  = (g < 3) ? 2 * g : 6;
    ull ea0[4] = {0,0,0,0}, ea1[4] = {0,0,0,0};
    {   // half 1: input channels par, par+2, ..., par+14
        const float* xb = sm + XPA_OFF + par * 108;
        const float* sb = sm + SHA_OFF + par * 72;
        const float* wb = sm + WR2_OFF + par * 297;   // par*9*33
        if (g < 3) conv_pair<true >(ea0, ea1, xb, sb, wb, 33, lane, p0, 8, 216, 144, 594);
        else       conv_pair<false>(ea0, ea1, xb, sb, wb, 33, lane, 6,  8, 216, 144, 594);
    }
    __syncthreads();
    for (int idx = t; idx < 4608; idx += 256) {    // stage w_res half 2
        int o = idx / 144, r = idx - o * 144;
        sm[WR2_OFF + r * 33 + o] = w_res[o * 288 + 144 + r];
    }
    __syncthreads();
    {   // half 2: input channels 16+par, 16+par+2, ...
        const float* xb = sm + XPA_OFF + (16 + par) * 108;
        const float* sb = sm + SHA_OFF + (16 + par) * 72;
        const float* wb = sm + WR2_OFF + par * 297;
        if (g < 3) conv_pair<true >(ea0, ea1, xb, sb, wb, 33, lane, p0, 8, 216, 144, 594);
        else       conv_pair<false>(ea0, ea1, xb, sb, wb, 33, lane, 6,  8, 216, 144, 594);
    }
    __syncthreads();   // conv reads of WR2 / shA done

    // E-merge phase 1: warps 4-7 park partials in dead WR2; warps 0-3 stage w2
    if (w >= 4) {
        float* s = sm + WR2_OFF + g * 640 + lane * 20;
        ((ulonglong2*)s)[0]       = make_ulonglong2(ea0[0], ea0[1]);
        ((ulonglong2*)(s + 4))[0] = make_ulonglong2(ea0[2], ea0[3]);
        if (g < 3) {
            ((ulonglong2*)(s + 8))[0]  = make_ulonglong2(ea1[0], ea1[1]);
            ((ulonglong2*)(s + 12))[0] = make_ulonglong2(ea1[2], ea1[3]);
        }
    } else {
        for (int idx = t; idx < 144; idx += 128) sm[W2_OFF + idx] = w2[idx];
    }
    __syncthreads();

    // E-merge phase 2: warps 0-3 add partner partials + BN + ReLU + residual -> regs
    // (NO shB/xpadB writes here: shB overlaps xpadA tail read as residual by g=3.
    //  All residual reads complete before the barrier below.)
    float er0[8], er1[8];
    if (w < 4) {
        const float* s = sm + WR2_OFF + g * 640 + lane * 20;
        {
            ulonglong2 pA = ((const ulonglong2*)s)[0];
            ulonglong2 pB = ((const ulonglong2*)(s + 4))[0];
            ea0[0] = add2(ea0[0], pA.x); ea0[1] = add2(ea0[1], pA.y);
            ea0[2] = add2(ea0[2], pB.x); ea0[3] = add2(ea0[3], pB.y);
        }
        if (g < 3) {
            ulonglong2 pA = ((const ulonglong2*)(s + 8))[0];
            ulonglong2 pB = ((const ulonglong2*)(s + 12))[0];
            ea1[0] = add2(ea1[0], pA.x); ea1[1] = add2(ea1[1], pA.y);
            ea1[2] = add2(ea1[2], pB.x); ea1[3] = add2(ea1[3], pB.y);
        }
        float sc = bnres_w[lane] * rsqrtf(bnres_v[lane] + EPSV);
        float bi = fmaf(b_res[lane], sc, bnres_b[lane] - bnres_m[lane] * sc);
        const float* rs0 = sm + XPA_OFF + lane * 108 + (p0 + 1) * 12 + 1;
        float r0[8];
        up2(ea0[0],r0[0],r0[1]); up2(ea0[1],r0[2],r0[3]);
        up2(ea0[2],r0[4],r0[5]); up2(ea0[3],r0[6],r0[7]);
        #pragma unroll
        for (int q = 0; q < 8; ++q) er0[q] = fmaxf(fmaf(r0[q], sc, bi), 0.f) + rs0[q];
        if (g < 3) {
            float r1[8];
            up2(ea1[0],r1[0],r1[1]); up2(ea1[1],r1[2],r1[3]);
            up2(ea1[2],r1[4],r1[5]); up2(ea1[3],r1[6],r1[7]);
            const float* rs1 = rs0 + 12;
            #pragma unroll
            for (int q = 0; q < 8; ++q) er1[q] = fmaxf(fmaf(r1[q], sc, bi), 0.f) + rs1[q];
        }
    }
    __syncthreads();   // all residual/shA reads + scratch reads done

    // write stage-E rows into xpadB/shB, zero shB pad rows, stage w1T concurrently
    if (w < 4) {
        int hoff = (lane >> 4) * 16;
        float* db0 = sm + XPB_OFF + lane * 108 + hoff + (p0 + 1) * 12 + 1;
        float* sb0 = sm + SHB_OFF + lane * 72 + hoff + (p0 + 1) * 8;
        #pragma unroll
        for (int q = 0; q < 8; ++q) { db0[q] = er0[q]; sb0[q] = er0[q]; }
        if (g < 3) {
            #pragma unroll
            for (int q = 0; q < 8; ++q) { db0[12 + q] = er1[q]; sb0[8 + q] = er1[q]; }
        }
    } else {
        for (int idx = t - 128; idx < 512; idx += 128) {   // zero shB pad rows 0 & 8
            int ch = idx >> 4, rem = idx & 15;
            int rowoff = (rem & 8) ? 64 : 0, q = rem & 7;
            sm[SHB_OFF + ch * 72 + (ch >> 4) * 16 + rowoff + q] = 0.f;
        }
    }
    for (int idx = t; idx < 4608; idx += 256) {    // w1T two halves, stride 17
        int o = idx / 288, rr = idx - o * 288;
        int half = (rr >= 144) ? 1 : 0, rp = rr - half * 144;
        sm[WR2_OFF + half * 2448 + rp * 17 + o] = w1[idx];
    }
    __syncthreads();

    // ============ Stage F: 3x3 conv 32->16, 8 warps: rows x parity, lane halves ===
    {
        int o16 = lane & 15, half = lane >> 4;
        const float* xb = sm + XPB_OFF + half * 1744 + par * 108;
        const float* sb = sm + SHB_OFF + half * 1168 + par * 72;
        const float* wb = sm + WR2_OFF + half * 2448 + par * 153;  // par*9*17
        ull fa0[4] = {0,0,0,0}, fa1[4] = {0,0,0,0};
        if (g < 3) conv_pair<true >(fa0, fa1, xb, sb, wb, 17, o16, p0, 8, 216, 144, 306);
        else       conv_pair<false>(fa0, fa1, xb, sb, wb, 17, o16, 6,  8, 216, 144, 306);
        #pragma unroll
        for (int m = 0; m < 4; ++m) {
            fa0[m] = add2(fa0[m], __shfl_xor_sync(0xffffffffu, fa0[m], 16));
            fa1[m] = add2(fa1[m], __shfl_xor_sync(0xffffffffu, fa1[m], 16));
        }
        if (w >= 4 && lane < 16) {   // park parity-1 partials in dead xpadA ch16+
            float* s = sm + FSCR_OFF + g * 320 + lane * 20;
            ((ulonglong2*)s)[0]       = make_ulonglong2(fa0[0], fa0[1]);
            ((ulonglong2*)(s + 4))[0] = make_ulonglong2(fa0[2], fa0[3]);
            if (g < 3) {
                ((ulonglong2*)(s + 8))[0]  = make_ulonglong2(fa1[0], fa1[1]);
                ((ulonglong2*)(s + 12))[0] = make_ulonglong2(fa1[2], fa1[3]);
            }
        }
        __syncthreads();
        if (w < 4 && lane < 16) {
            const float* s = sm + FSCR_OFF + g * 320 + lane * 20;
            {
                ulonglong2 pA = ((const ulonglong2*)s)[0];
                ulonglong2 pB = ((const ulonglong2*)(s + 4))[0];
                fa0[0] = add2(fa0[0], pA.x); fa0[1] = add2(fa0[1], pA.y);
                fa0[2] = add2(fa0[2], pB.x); fa0[3] = add2(fa0[3], pB.y);
            }
            if (g < 3) {
                ulonglong2 pA = ((const ulonglong2*)(s + 8))[0];
                ulonglong2 pB = ((const ulonglong2*)(s + 12))[0];
                fa1[0] = add2(fa1[0], pA.x); fa1[1] = add2(fa1[1], pA.y);
                fa1[2] = add2(fa1[2], pB.x); fa1[3] = add2(fa1[3], pB.y);
            }
            float sc = bn1_w[o16] * rsqrtf(bn1_v[o16] + EPSV);
            float bi = fmaf(b1[o16], sc, bn1_b[o16] - bn1_m[o16] * sc);
            float r0[8];
            up2(fa0[0],r0[0],r0[1]); up2(fa0[1],r0[2],r0[3]);
            up2(fa0[2],r0[4],r0[5]); up2(fa0[3],r0[6],r0[7]);
            float* dst = sm + XPA_OFF + o16 * 108 + (p0 + 1) * 12 + 1;
            #pragma unroll
            for (int q = 0; q < 8; ++q) dst[q] = fmaxf(fmaf(r0[q], sc, bi), 0.f);
            if (g < 3) {
                float r1[8];
                up2(fa1[0],r1[0],r1[1]); up2(fa1[1],r1[2],r1[3]);
                up2(fa1[2],r1[4],r1[5]); up2(fa1[3],r1[6],r1[7]);
                #pragma unroll
                for (int q = 0; q < 8; ++q) dst[12 + q] = fmaxf(fmaf(r1[q], sc, bi), 0.f);
            }
        }
    }
    __syncthreads();

    // ============ Stage G: conv2 3x3 16->1 ============
    if (t < 56) {
        int p = t >> 3, q = t & 7;
        float acc2 = b2[0];
        #pragma unroll 4
        for (int i = 0; i < 16; ++i) {
            const float* xc = sm + XPA_OFF + i * 108 + p * 12 + q;
            const float* wg = sm + W2_OFF + i * 9;
            acc2 = fmaf(wg[0], xc[0],  acc2);
            acc2 = fmaf(wg[1], xc[1],  acc2);
            acc2 = fmaf(wg[2], xc[2],  acc2);
            acc2 = fmaf(wg[3], xc[12], acc2);
            acc2 = fmaf(wg[4], xc[13], acc2);
            acc2 = fmaf(wg[5], xc[14], acc2);
            acc2 = fmaf(wg[6], xc[24], acc2);
            acc2 = fmaf(wg[7], xc[25], acc2);
            acc2 = fmaf(wg[8], xc[26], acc2);
        }
        out[(size_t)b * 56 + t] = acc2;
    }
}

extern "C" void kernel_launch(void* const* d_in, const int* in_sizes, int n_in,
                              void* d_out, int out_size) {
    const float* mg      = (const float*)d_in[0];
    const float* w_cr    = (const float*)d_in[1];
    const float* b_cr    = (const float*)d_in[2];
    const float* bnr_w   = (const float*)d_in[3];
    const float* bnr_b   = (const float*)d_in[4];
    const float* bnr_m   = (const float*)d_in[5];
    const float* bnr_v   = (const float*)d_in[6];
    const float* q_w     = (const float*)d_in[7];
    const float* q_b     = (const float*)d_in[8];
    const float* k_w     = (const float*)d_in[9];
    const float* k_b     = (const float*)d_in[10];
    const float* v_w     = (const float*)d_in[11];
    const float* v_b     = (const float*)d_in[12];
    const float* gamma   = (const float*)d_in[13];
    const float* ln_w    = (const float*)d_in[14];
    const float* ln_b    = (const float*)d_in[15];
    const float* w_res   = (const float*)d_in[16];
    const float* b_res   = (const float*)d_in[17];
    const float* bnres_w = (const float*)d_in[18];
    const float* bnres_b = (const float*)d_in[19];
    const float* bnres_m = (const float*)d_in[20];
    const float* bnres_v = (const float*)d_in[21];
    const float* w1      = (const float*)d_in[22];
    const float* b1      = (const float*)d_in[23];
    const float* bn1_w   = (const float*)d_in[24];
    const float* bn1_b   = (const float*)d_in[25];
    const float* bn1_m   = (const float*)d_in[26];
    const float* bn1_v   = (const float*)d_in[27];
    const float* w2      = (const float*)d_in[28];
    const float* b2      = (const float*)d_in[29];

    int B = in_sizes[0] / 32768;
    size_t smem_bytes = SMEM_FLOATS * sizeof(float);   // 56KB -> 4 CTAs/SM
    cudaFuncSetAttribute(occ_fused_kernel,
                         cudaFuncAttributeMaxDynamicSharedMemorySize, (int)smem_bytes);
    occ_fused_kernel<<<B, 256, smem_bytes>>>(
        mg, w_cr, b_cr, bnr_w, bnr_b, bnr_m, bnr_v,
        q_w, q_b, k_w, k_b, v_w, v_b, gamma, ln_w, ln_b,
        w_res, b_res, bnres_w, bnres_b, bnres_m, bnres_v,
        w1, b1, bn1_w, bn1_b, bn1_m, bn1_v, w2, b2,
        (float*)d_out);
}

// round 17
// speedup vs baseline: 1.4168x; 1.0029x over previous
#include <cuda_runtime.h>

#define EPSV 1e-5f
typedef unsigned long long ull;

// ---------------- shared memory layout (float offsets), 14336 floats = 56KB --
// Phase 1:
//   [0,7168)      pooled[128][56]
//     after stage B (pooled+wcrT dead): QT[4][60]@0, KT[4][60]@240,
//        VT[56][32]@480, S[56][60]@2272..5632, attnT[56][60]@5632..8992,
//        RED@8992..9024
//   [7168,11392)  wcrT as 64 c-pairs x 33 ull slots (4224 floats; dead after B)
//   [11392,12416) vTw[32][32]
//   [12416,14336) xbuf[32][60]
// Phase 2:
//   [0,3456)      xpadA[32][9][12]   (ch16+ region reused as F-merge scratch)
//   [3456,5760)   shA[32][9][8]
//   [3424,5760)   shB (aliases shA + 32-float XPA tail; halves @3424/4592)
//   [5760,9248)   xpadB 2 halves of [16][9][12], half stride 1744
//   [9248,14000)  wres half [144][33]=4752 (reused as E-merge scratch);
//                 later w1T 2x[144][17] @9248/11696
//   [14144,14288) w2
#define POOL_OFF 0
#define QT_OFF   0
#define KT_OFF   240
#define VT_OFF   480
#define S_OFF    2272
#define ATT_OFF  5632
#define RED_OFF  8992
#define WCRT_OFF 7168
#define VTW_OFF  11392
#define XBUF_OFF 12416

#define XPA_OFF  0
#define SHA_OFF  3456
#define SHB_OFF  3424
#define XPB_OFF  5760
#define WR2_OFF  9248
#define W2_OFF   14144
#define SMEM_FLOATS 14336

#define FSCR_OFF (XPA_OFF + 1728)   // F-merge scratch (dead xpadA ch16+)

// ---------------- packed f32x2 helpers ----------------
__device__ __forceinline__ ull pk2(float x, float y) {
    ull r; asm("mov.b64 %0, {%1, %2};" : "=l"(r) : "f"(x), "f"(y)); return r;
}
__device__ __forceinline__ void up2(ull v, float& x, float& y) {
    asm("mov.b64 {%0, %1}, %2;" : "=f"(x), "=f"(y) : "l"(v));
}
__device__ __forceinline__ ull fma2(ull a, ull b, ull c) {
    ull r; asm("fma.rn.f32x2 %0, %1, %2, %3;" : "=l"(r) : "l"(a), "l"(b), "l"(c)); return r;
}
__device__ __forceinline__ ull add2(ull a, ull b) {
    ull r; asm("add.rn.f32x2 %0, %1, %2;" : "=l"(r) : "l"(a), "l"(b)); return r;
}

// 8-wide GEMM step: acc[4] += w * x[0..7], x warp-uniform (broadcast LDS.128)
// REQUIREMENT: x must be 16B-aligned (float offset % 4 == 0)
__device__ __forceinline__ void g8(ull acc[4], const float* __restrict__ x, float wv) {
    ulonglong2 A = *(const ulonglong2*)(x);
    ulonglong2 B = *(const ulonglong2*)(x + 4);
    ull wp = pk2(wv, wv);
    acc[0] = fma2(wp, A.x, acc[0]); acc[1] = fma2(wp, A.y, acc[1]);
    acc[2] = fma2(wp, B.x, acc[2]); acc[3] = fma2(wp, B.y, acc[3]);
}

// one 3-tap row application: 12 FFMA2 for 8 outputs
__device__ __forceinline__ void apply9(ull acc[4], const ull* __restrict__ W,
        const ulonglong2& E01, const ulonglong2& E23, ull E4,
        const ulonglong2& O01, const ulonglong2& O23) {
    acc[0] = fma2(W[0], E01.x, acc[0]); acc[1] = fma2(W[0], E01.y, acc[1]);
    acc[2] = fma2(W[0], E23.x, acc[2]); acc[3] = fma2(W[0], E23.y, acc[3]);
    acc[0] = fma2(W[1], O01.x, acc[0]); acc[1] = fma2(W[1], O01.y, acc[1]);
    acc[2] = fma2(W[1], O23.x, acc[2]); acc[3] = fma2(W[1], O23.y, acc[3]);
    acc[0] = fma2(W[2], E01.y, acc[0]); acc[1] = fma2(W[2], E23.x, acc[1]);
    acc[2] = fma2(W[2], E23.y, acc[2]); acc[3] = fma2(W[2], E4,    acc[3]);
}

// 3x3 conv over nch channels (channel steps xstep/sstep/wstep allow parity
// splits), output rows p0 (and p0+1 if TWO). Weights loaded once per channel.
// E4 = (x8, 0) reconstructed from O23.y (x9 is always pad-zero).
template<bool TWO>
__device__ __forceinline__ void conv_pair(ull a0[4], ull a1[4],
    const float* __restrict__ xb, const float* __restrict__ sb,
    const float* __restrict__ wb, int ws, int o, int p0, int nch,
    int xstep, int sstep, int wstep) {
    #pragma unroll 1
    for (int ch = 0; ch < nch; ++ch) {
        const float* wp = wb + ch * wstep + o;
        ull W[9];
        #pragma unroll
        for (int k = 0; k < 9; ++k) { float wv = wp[k * ws]; W[k] = pk2(wv, wv); }
        const float* xrow = xb + ch * xstep + p0 * 12;
        const float* srow = sb + ch * sstep + p0 * 8;
        #pragma unroll
        for (int r = 0; r < (TWO ? 4 : 3); ++r) {
            ulonglong2 E01 = *(const ulonglong2*)(xrow + r * 12);
            ulonglong2 E23 = *(const ulonglong2*)(xrow + r * 12 + 4);
            ulonglong2 O01 = *(const ulonglong2*)(srow + r * 8);
            ulonglong2 O23 = *(const ulonglong2*)(srow + r * 8 + 4);
            ull E4 = O23.y >> 32;                 // (x8, 0)
            if (r < 3)         apply9(a0, W + 3 * r,       E01, E23, E4, O01, O23);
            if (TWO && r >= 1) apply9(a1, W + 3 * (r - 1), E01, E23, E4, O01, O23);
        }
    }
}

__global__ void __launch_bounds__(256, 4) occ_fused_kernel(
    const float* __restrict__ mg,
    const float* __restrict__ w_cr, const float* __restrict__ b_cr,
    const float* __restrict__ bnr_w, const float* __restrict__ bnr_b,
    const float* __restrict__ bnr_m, const float* __restrict__ bnr_v,
    const float* __restrict__ q_w,  const float* __restrict__ q_b,
    const float* __restrict__ k_w,  const float* __restrict__ k_b,
    const float* __restrict__ v_w,  const float* __restrict__ v_b,
    const float* __restrict__ gamma,
    const float* __restrict__ ln_w, const float* __restrict__ ln_b,
    const float* __restrict__ w_res, const float* __restrict__ b_res,
    const float* __restrict__ bnres_w, const float* __restrict__ bnres_b,
    const float* __restrict__ bnres_m, const float* __restrict__ bnres_v,
    const float* __restrict__ w1,  const float* __restrict__ b1,
    const float* __restrict__ bn1_w, const float* __restrict__ bn1_b,
    const float* __restrict__ bn1_m, const float* __restrict__ bn1_v,
    const float* __restrict__ w2,  const float* __restrict__ b2,
    float* __restrict__ out)
{
    extern __shared__ float sm[];
    const int t = threadIdx.x;
    const int b = blockIdx.x;
    const int w = t >> 5;
    const int lane = t & 31;
    float* red = sm + RED_OFF;

    // ============ Stage A: coalesced shuffle-pooling 16x16 -> 7x8 + weights =======
    {
        const float* in = mg + (size_t)b * 32768;
        const int cg = lane & 3;
        const int pp = lane >> 2;                           // output p (lanes <28)
        const int sA = cg + pp * 8;                         // rows 0,2,4 for p=0,1,2
        const int sB = cg + (pp - 4) * 8 + 4;               // rows 9,11,13 for p=4,5,6
        const float scale = (pp == 3) ? 0.125f : 0.16666667f;
        #pragma unroll 1
        for (int i = 0; i < 16; ++i) {
            int c = w * 16 + i;
            const float4* base = (const float4*)(in + c * 256);
            float4 v0 = base[lane];
            float4 v1 = base[lane + 32];
            float a0 = v0.x + v0.y, b0 = v0.z + v0.w;       // row lane>>2
            float a1 = v1.x + v1.y, b1 = v1.z + v1.w;       // row 8+(lane>>2)
            float a0d4 = __shfl_down_sync(0xffffffffu, a0, 4);
            float a0d8 = __shfl_down_sync(0xffffffffu, a0, 8);
            float b0d4 = __shfl_down_sync(0xffffffffu, b0, 4);
            float b0d8 = __shfl_down_sync(0xffffffffu, b0, 8);
            float a1d4 = __shfl_down_sync(0xffffffffu, a1, 4);
            float a1d8 = __shfl_down_sync(0xffffffffu, a1, 8);
            float b1d4 = __shfl_down_sync(0xffffffffu, b1, 4);
            float b1d8 = __shfl_down_sync(0xffffffffu, b1, 8);
            float P2a0 = a0 + a0d4,  P2b0 = b0 + b0d4;
            float P2a1 = a1 + a1d4,  P2b1 = b1 + b1d4;
            float A3a0 = P2a0 + a0d8, A3b0 = P2b0 + b0d8;
            float A3a1 = P2a1 + a1d8, A3b1 = P2b1 + b1d8;
            float gAa = __shfl_sync(0xffffffffu, A3a0, sA);
            float gAb = __shfl_sync(0xffffffffu, A3b0, sA);
            float gBa = __shfl_sync(0xffffffffu, A3a1, sB);
            float gBb = __shfl_sync(0xffffffffu, A3b1, sB);
            float gP0a = __shfl_sync(0xffffffffu, P2a0, cg + 24);
            float gP0b = __shfl_sync(0xffffffffu, P2b0, cg + 24);
            float gP1a = __shfl_sync(0xffffffffu, P2a1, cg);
            float gP1b = __shfl_sync(0xffffffffu, P2b1, cg);
            if (lane < 28) {
                float ra = (pp < 3) ? gAa : (pp == 3) ? (gP0a + gP1a) : gBa;
                float rb = (pp < 3) ? gAb : (pp == 3) ? (gP0b + gP1b) : gBb;
                *(float2*)(sm + POOL_OFF + c * 56 + lane * 2) =
                    make_float2(ra * scale, rb * scale);
            }
        }
        // wcrT c-pair staging, conflict-light: lane = c-pair (cp), FULL coverage:
        // 8 iterations x 256 threads x 1 ull = 2048 ulls = 64 cp x 32 o.
        // LDG float2 coalesced (256B/warp); STS.64 at 66*cp + 2o -> 2-way max.
        #pragma unroll
        for (int k = 0; k < 8; ++k) {
            int o  = (t >> 5) + (k >> 1) * 8;
            int cp = (t & 31) + (k & 1) * 32;
            float2 wv = *(const float2*)(w_cr + o * 128 + cp * 2);
            *(ull*)(sm + WCRT_OFF + cp * 66 + o * 2) = pk2(wv.x, wv.y);
        }
        {   // vTw[in][o]: lane = o -> fully-coalesced conflict-free STS
            int o = lane, in4 = (t >> 5) * 4;
            float4 vv = *(const float4*)(v_w + o * 32 + in4);
            sm[VTW_OFF + (in4 + 0) * 32 + o] = vv.x;
            sm[VTW_OFF + (in4 + 1) * 32 + o] = vv.y;
            sm[VTW_OFF + (in4 + 2) * 32 + o] = vv.z;
            sm[VTW_OFF + (in4 + 3) * 32 + o] = vv.w;
        }
    }
    __syncthreads();

    // ============ Stage B: 1x1 128->32 + BN + ReLU. warp=p, lane=o ============
    if (w < 7) {
        ull a[4] = {0,0,0,0};
        const float* xb = sm + POOL_OFF + w * 8;
        const float* wc = sm + WCRT_OFF + lane * 2;
        #pragma unroll 4
        for (int cp = 0; cp < 64; ++cp) {
            ull wpair = *(const ull*)(wc + cp * 66);
            float w0, w1; up2(wpair, w0, w1);
            g8(a, xb + (2 * cp) * 56, w0);
            g8(a, xb + (2 * cp + 1) * 56, w1);
        }
        float sc = bnr_w[lane] * rsqrtf(bnr_v[lane] + EPSV);
        float bi = fmaf(b_cr[lane], sc, bnr_b[lane] - bnr_m[lane] * sc);
        float r[8];
        up2(a[0],r[0],r[1]); up2(a[1],r[2],r[3]); up2(a[2],r[4],r[5]); up2(a[3],r[6],r[7]);
        float* dst = sm + XBUF_OFF + lane * 60 + w * 8;
        #pragma unroll
        for (int q = 0; q < 8; ++q) dst[q] = fmaxf(fmaf(r[q], sc, bi), 0.f);
    }
    __syncthreads();

    // ============ Stage C1: v (warps 0-6), q & k (warp 7, weights via gmem) =======
    if (w < 7) {
        float bias = v_b[lane];
        ull a[4]; a[0]=a[1]=a[2]=a[3]=pk2(bias,bias);
        const float* xb = sm + XBUF_OFF + w * 8;
        const float* wv2p = sm + VTW_OFF + lane;
        #pragma unroll 4
        for (int in2 = 0; in2 < 32; ++in2)
            g8(a, xb + in2 * 60, wv2p[in2 * 32]);
        float r[8];
        up2(a[0],r[0],r[1]); up2(a[1],r[2],r[3]); up2(a[2],r[4],r[5]); up2(a[3],r[6],r[7]);
        #pragma unroll
        for (int q = 0; q < 8; ++q) sm[VT_OFF + (w * 8 + q) * 32 + lane] = r[q];
    } else if (lane < 28) {
        int d = lane / 7, p = lane - d * 7;
        const float* xb = sm + XBUF_OFF + p * 8;
        #pragma unroll
        for (int pass = 0; pass < 2; ++pass) {
            const float* W = (pass ? k_w : q_w) + d * 32;
            float bias = pass ? k_b[d] : q_b[d];
            ull a[4]; a[0]=a[1]=a[2]=a[3]=pk2(bias,bias);
            for (int in2 = 0; in2 < 32; ++in2) g8(a, xb + in2 * 60, __ldg(W + in2));
            float r[8];
            up2(a[0],r[0],r[1]); up2(a[1],r[2],r[3]); up2(a[2],r[4],r[5]); up2(a[3],r[6],r[7]);
            float* dst = sm + (pass ? KT_OFF : QT_OFF) + d * 60 + p * 8;
            #pragma unroll
            for (int q = 0; q < 8; ++q) dst[q] = r[q];
        }
    }
    __syncthreads();

    // ============ Stage C2: S[i][j] = sum_d q[d][i] k[d][j] ============
    if (w < 7) {
        int i0 = w * 8;
        #pragma unroll
        for (int seg = 0; seg < 2; ++seg) {
            int j = seg * 32 + lane;
            if (j < 56) {
                ull a[4] = {0,0,0,0};
                #pragma unroll
                for (int d = 0; d < 4; ++d)
                    g8(a, sm + QT_OFF + d * 60 + i0, sm[KT_OFF + d * 60 + j]);
                float r[8];
                up2(a[0],r[0],r[1]); up2(a[1],r[2],r[3]); up2(a[2],r[4],r[5]); up2(a[3],r[6],r[7]);
                #pragma unroll
                for (int q = 0; q < 8; ++q) sm[S_OFF + (i0 + q) * 60 + j] = r[q];
            }
        }
    }
    __syncthreads();

    // ============ softmax: 8 warps x 7 rows, shfl reductions, write attnT[j][i] ===
    {
        int i0 = w * 7;
        #pragma unroll 1
        for (int rr = 0; rr < 7; ++rr) {
            int i = i0 + rr;
            const float* row = sm + S_OFF + i * 60;
            float v0 = row[lane];
            float v1 = (lane < 24) ? row[32 + lane] : -1e30f;
            float m = fmaxf(v0, v1);
            #pragma unroll
            for (int off = 16; off; off >>= 1)
                m = fmaxf(m, __shfl_xor_sync(0xffffffffu, m, off));
            float e0 = __expf(v0 - m);
            float e1 = (lane < 24) ? __expf(v1 - m) : 0.f;
            float ssum = e0 + e1;
            #pragma unroll
            for (int off = 16; off; off >>= 1)
                ssum += __shfl_xor_sync(0xffffffffu, ssum, off);
            float inv = 1.f / ssum;
            sm[ATT_OFF + lane * 60 + i] = e0 * inv;
            if (lane < 24) sm[ATT_OFF + (32 + lane) * 60 + i] = e1 * inv;
        }
    }
    __syncthreads();

    // ============ Stage C3: out[c][i] = sum_j v[j][c]*attnT[j][i]; x += gamma*out ==
    if (w < 7) {
        int i0 = w * 8;
        ull a[4] = {0,0,0,0};
        #pragma unroll 4
        for (int j = 0; j < 56; ++j)
            g8(a, sm + ATT_OFF + j * 60 + i0, sm[VT_OFF + j * 32 + lane]);
        float r[8];
        up2(a[0],r[0],r[1]); up2(a[1],r[2],r[3]); up2(a[2],r[4],r[5]); up2(a[3],r[6],r[7]);
        float g = gamma[0];
        float* xr = sm + XBUF_OFF + lane * 60 + i0;
        #pragma unroll
        for (int q = 0; q < 8; ++q) xr[q] = fmaf(g, r[q], xr[q]);
    }
    __syncthreads();

    // ============ Stage D: LayerNorm over 1792 ============
    float vals[7];
    {
        float s1 = 0.f, s2 = 0.f;
        int c = t / 56, s = t - c * 56;
        #pragma unroll
        for (int k = 0; k < 7; ++k) {
            float x = sm[XBUF_OFF + c * 60 + s];
            vals[k] = x; s1 += x; s2 = fmaf(x, x, s2);
            s += 32; c += 4; if (s >= 56) { s -= 56; ++c; }
        }
        #pragma unroll
        for (int off = 16; off; off >>= 1) {
            s1 += __shfl_xor_sync(0xffffffffu, s1, off);
            s2 += __shfl_xor_sync(0xffffffffu, s2, off);
        }
        if (lane == 0) { red[w] = s1; red[8 + w] = s2; }
        __syncthreads();
        if (t == 0) {
            float S1 = 0.f, S2 = 0.f;
            for (int k = 0; k < 8; ++k) { S1 += red[k]; S2 += red[8 + k]; }
            float mu = S1 * (1.f / 1792.f);
            float var = S2 * (1.f / 1792.f) - mu * mu;
            red[16] = mu; red[17] = rsqrtf(var + EPSV);
        }
        __syncthreads();
        float mu = red[16], inv = red[17];
        #pragma unroll
        for (int k = 0; k < 7; ++k) {
            int v = t + k * 256;
            vals[k] = (vals[k] - mu) * inv * ln_w[v] + ln_b[v];
        }
    }
    __syncthreads();   // all phase-1 activation reads done

    // zero phase-2 activation region [0,9248) + stage w_res half 1
    {
        float4 z4 = make_float4(0.f, 0.f, 0.f, 0.f);
        float4* z = (float4*)sm;
        for (int idx = t; idx < 2312; idx += 256) z[idx] = z4;
        for (int idx = t; idx < 4608; idx += 256) {
            int o = idx / 144, r = idx - o * 144;
            sm[WR2_OFF + r * 33 + o] = w_res[o * 288 + r];
        }
    }
    __syncthreads();
    {
        int c = t / 56, s = t - c * 56;
        #pragma unroll
        for (int k = 0; k < 7; ++k) {   // scatter LN output into xpadA + shifted shA
            int p = s >> 3, q = s & 7;
            sm[XPA_OFF + c * 108 + (p + 1) * 12 + (q + 1)] = vals[k];
            sm[SHA_OFF + c * 72 + (p + 1) * 8 + q] = vals[k];
            s += 32; c += 4; if (s >= 56) { s -= 56; ++c; }
        }
    }
    __syncthreads();

    // ============ Stage E: 3x3 conv 32->32, 8 warps: row-pair (g) x parity (par) ==
    const int g   = w & 3;
    const int par = w >> 2;
    const int p0  = (g < 3) ? 2 * g : 6;
    ull ea0[4] = {0,0,0,0}, ea1[4] = {0,0,0,0};
    {   // half 1: input channels par, par+2, ..., par+14
        const float* xb = sm + XPA_OFF + par * 108;
        const float* sb = sm + SHA_OFF + par * 72;
        const float* wb = sm + WR2_OFF + par * 297;   // par*9*33
        if (g < 3) conv_pair<true >(ea0, ea1, xb, sb, wb, 33, lane, p0, 8, 216, 144, 594);
        else       conv_pair<false>(ea0, ea1, xb, sb, wb, 33, lane, 6,  8, 216, 144, 594);
    }
    __syncthreads();
    for (int idx = t; idx < 4608; idx += 256) {    // stage w_res half 2
        int o = idx / 144, r = idx - o * 144;
        sm[WR2_OFF + r * 33 + o] = w_res[o * 288 + 144 + r];
    }
    __syncthreads();
    {   // half 2: input channels 16+par, 16+par+2, ...
        const float* xb = sm + XPA_OFF + (16 + par) * 108;
        const float* sb = sm + SHA_OFF + (16 + par) * 72;
        const float* wb = sm + WR2_OFF + par * 297;
        if (g < 3) conv_pair<true >(ea0, ea1, xb, sb, wb, 33, lane, p0, 8, 216, 144, 594);
        else       conv_pair<false>(ea0, ea1, xb, sb, wb, 33, lane, 6,  8, 216, 144, 594);
    }
    __syncthreads();   // conv reads of WR2 / shA done

    // E-merge phase 1: warps 4-7 park partials in dead WR2; warps 0-3 stage w2
    if (w >= 4) {
        float* s = sm + WR2_OFF + g * 640 + lane * 20;
        ((ulonglong2*)s)[0]       = make_ulonglong2(ea0[0], ea0[1]);
        ((ulonglong2*)(s + 4))[0] = make_ulonglong2(ea0[2], ea0[3]);
        if (g < 3) {
            ((ulonglong2*)(s + 8))[0]  = make_ulonglong2(ea1[0], ea1[1]);
            ((ulonglong2*)(s + 12))[0] = make_ulonglong2(ea1[2], ea1[3]);
        }
    } else {
        for (int idx = t; idx < 144; idx += 128) sm[W2_OFF + idx] = w2[idx];
    }
    __syncthreads();

    // E-merge phase 2: warps 0-3 add partner partials + BN + ReLU + residual -> regs
    float er0[8], er1[8];
    if (w < 4) {
        const float* s = sm + WR2_OFF + g * 640 + lane * 20;
        {
            ulonglong2 pA = ((const ulonglong2*)s)[0];
            ulonglong2 pB = ((const ulonglong2*)(s + 4))[0];
            ea0[0] = add2(ea0[0], pA.x); ea0[1] = add2(ea0[1], pA.y);
            ea0[2] = add2(ea0[2], pB.x); ea0[3] = add2(ea0[3], pB.y);
        }
        if (g < 3) {
            ulonglong2 pA = ((const ulonglong2*)(s + 8))[0];
            ulonglong2 pB = ((const ulonglong2*)(s + 12))[0];
            ea1[0] = add2(ea1[0], pA.x); ea1[1] = add2(ea1[1], pA.y);
            ea1[2] = add2(ea1[2], pB.x); ea1[3] = add2(ea1[3], pB.y);
        }
        float sc = bnres_w[lane] * rsqrtf(bnres_v[lane] + EPSV);
        float bi = fmaf(b_res[lane], sc, bnres_b[lane] - bnres_m[lane] * sc);
        const float* rs0 = sm + XPA_OFF + lane * 108 + (p0 + 1) * 12 + 1;
        float r0[8];
        up2(ea0[0],r0[0],r0[1]); up2(ea0[1],r0[2],r0[3]);
        up2(ea0[2],r0[4],r0[5]); up2(ea0[3],r0[6],r0[7]);
        #pragma unroll
        for (int q = 0; q < 8; ++q) er0[q] = fmaxf(fmaf(r0[q], sc, bi), 0.f) + rs0[q];
        if (g < 3) {
            float r1[8];
            up2(ea1[0],r1[0],r1[1]); up2(ea1[1],r1[2],r1[3]);
            up2(ea1[2],r1[4],r1[5]); up2(ea1[3],r1[6],r1[7]);
            const float* rs1 = rs0 + 12;
            #pragma unroll
            for (int q = 0; q < 8; ++q) er1[q] = fmaxf(fmaf(r1[q], sc, bi), 0.f) + rs1[q];
        }
    }
    __syncthreads();   // all residual/shA reads + scratch reads done

    // write stage-E rows into xpadB/shB, zero shB pad rows, stage w1T concurrently
    if (w < 4) {
        int hoff = (lane >> 4) * 16;
        float* db0 = sm + XPB_OFF + lane * 108 + hoff + (p0 + 1) * 12 + 1;
        float* sb0 = sm + SHB_OFF + lane * 72 + hoff + (p0 + 1) * 8;
        #pragma unroll
        for (int q = 0; q < 8; ++q) { db0[q] = er0[q]; sb0[q] = er0[q]; }
        if (g < 3) {
            #pragma unroll
            for (int q = 0; q < 8; ++q) { db0[12 + q] = er1[q]; sb0[8 + q] = er1[q]; }
        }
    } else {
        for (int idx = t - 128; idx < 512; idx += 128) {   // zero shB pad rows 0 & 8
            int ch = idx >> 4, rem = idx & 15;
            int rowoff = (rem & 8) ? 64 : 0, q = rem & 7;
            sm[SHB_OFF + ch * 72 + (ch >> 4) * 16 + rowoff + q] = 0.f;
        }
    }
    for (int idx = t; idx < 4608; idx += 256) {    // w1T two halves, stride 17
        int o = idx / 288, rr = idx - o * 288;
        int half = (rr >= 144) ? 1 : 0, rp = rr - half * 144;
        sm[WR2_OFF + half * 2448 + rp * 17 + o] = w1[idx];
    }
    __syncthreads();

    // ============ Stage F: 3x3 conv 32->16, 8 warps: rows x parity, lane halves ===
    {
        int o16 = lane & 15, half = lane >> 4;
        const float* xb = sm + XPB_OFF + half * 1744 + par * 108;
        const float* sb = sm + SHB_OFF + half * 1168 + par * 72;
        const float* wb = sm + WR2_OFF + half * 2448 + par * 153;  // par*9*17
        ull fa0[4] = {0,0,0,0}, fa1[4] = {0,0,0,0};
        if (g < 3) conv_pair<true >(fa0, fa1, xb, sb, wb, 17, o16, p0, 8, 216, 144, 306);
        else       conv_pair<false>(fa0, fa1, xb, sb, wb, 17, o16, 6,  8, 216, 144, 306);
        #pragma unroll
        for (int m = 0; m < 4; ++m) {
            fa0[m] = add2(fa0[m], __shfl_xor_sync(0xffffffffu, fa0[m], 16));
            fa1[m] = add2(fa1[m], __shfl_xor_sync(0xffffffffu, fa1[m], 16));
        }
        if (w >= 4 && lane < 16) {   // park parity-1 partials in dead xpadA ch16+
            float* s = sm + FSCR_OFF + g * 320 + lane * 20;
            ((ulonglong2*)s)[0]       = make_ulonglong2(fa0[0], fa0[1]);
            ((ulonglong2*)(s + 4))[0] = make_ulonglong2(fa0[2], fa0[3]);
            if (g < 3) {
                ((ulonglong2*)(s + 8))[0]  = make_ulonglong2(fa1[0], fa1[1]);
                ((ulonglong2*)(s + 12))[0] = make_ulonglong2(fa1[2], fa1[3]);
            }
        }
        __syncthreads();
        if (w < 4 && lane < 16) {
            const float* s = sm + FSCR_OFF + g * 320 + lane * 20;
            {
                ulonglong2 pA = ((const ulonglong2*)s)[0];
                ulonglong2 pB = ((const ulonglong2*)(s + 4))[0];
                fa0[0] = add2(fa0[0], pA.x); fa0[1] = add2(fa0[1], pA.y);
                fa0[2] = add2(fa0[2], pB.x); fa0[3] = add2(fa0[3], pB.y);
            }
            if (g < 3) {
                ulonglong2 pA = ((const ulonglong2*)(s + 8))[0];
                ulonglong2 pB = ((const ulonglong2*)(s + 12))[0];
                fa1[0] = add2(fa1[0], pA.x); fa1[1] = add2(fa1[1], pA.y);
                fa1[2] = add2(fa1[2], pB.x); fa1[3] = add2(fa1[3], pB.y);
            }
            float sc = bn1_w[o16] * rsqrtf(bn1_v[o16] + EPSV);
            float bi = fmaf(b1[o16], sc, bn1_b[o16] - bn1_m[o16] * sc);
            float r0[8];
            up2(fa0[0],r0[0],r0[1]); up2(fa0[1],r0[2],r0[3]);
            up2(fa0[2],r0[4],r0[5]); up2(fa0[3],r0[6],r0[7]);
            float* dst = sm + XPA_OFF + o16 * 108 + (p0 + 1) * 12 + 1;
            #pragma unroll
            for (int q = 0; q < 8; ++q) dst[q] = fmaxf(fmaf(r0[q], sc, bi), 0.f);
            if (g < 3) {
                float r1[8];
                up2(fa1[0],r1[0],r1[1]); up2(fa1[1],r1[2],r1[3]);
                up2(fa1[2],r1[4],r1[5]); up2(fa1[3],r1[6],r1[7]);
                #pragma unroll
                for (int q = 0; q < 8; ++q) dst[12 + q] = fmaxf(fmaf(r1[q], sc, bi), 0.f);
            }
        }
    }
    __syncthreads();

    // ============ Stage G: conv2 3x3 16->1 ============
    if (t < 56) {
        int p = t >> 3, q = t & 7;
        float acc2 = b2[0];
        #pragma unroll 4
        for (int i = 0; i < 16; ++i) {
            const float* xc = sm + XPA_OFF + i * 108 + p * 12 + q;
            const float* wg = sm + W2_OFF + i * 9;
            acc2 = fmaf(wg[0], xc[0],  acc2);
            acc2 = fmaf(wg[1], xc[1],  acc2);
            acc2 = fmaf(wg[2], xc[2],  acc2);
            acc2 = fmaf(wg[3], xc[12], acc2);
            acc2 = fmaf(wg[4], xc[13], acc2);
            acc2 = fmaf(wg[5], xc[14], acc2);
            acc2 = fmaf(wg[6], xc[24], acc2);
            acc2 = fmaf(wg[7], xc[25], acc2);
            acc2 = fmaf(wg[8], xc[26], acc2);
        }
        out[(size_t)b * 56 + t] = acc2;
    }
}

extern "C" void kernel_launch(void* const* d_in, const int* in_sizes, int n_in,
                              void* d_out, int out_size) {
    const float* mg      = (const float*)d_in[0];
    const float* w_cr    = (const float*)d_in[1];
    const float* b_cr    = (const float*)d_in[2];
    const float* bnr_w   = (const float*)d_in[3];
    const float* bnr_b   = (const float*)d_in[4];
    const float* bnr_m   = (const float*)d_in[5];
    const float* bnr_v   = (const float*)d_in[6];
    const float* q_w     = (const float*)d_in[7];
    const float* q_b     = (const float*)d_in[8];
    const float* k_w     = (const float*)d_in[9];
    const float* k_b     = (const float*)d_in[10];
    const float* v_w     = (const float*)d_in[11];
    const float* v_b     = (const float*)d_in[12];
    const float* gamma   = (const float*)d_in[13];
    const float* ln_w    = (const float*)d_in[14];
    const float* ln_b    = (const float*)d_in[15];
    const float* w_res   = (const float*)d_in[16];
    const float* b_res   = (const float*)d_in[17];
    const float* bnres_w = (const float*)d_in[18];
    const float* bnres_b = (const float*)d_in[19];
    const float* bnres_m = (const float*)d_in[20];
    const float* bnres_v = (const float*)d_in[21];
    const float* w1      = (const float*)d_in[22];
    const float* b1      = (const float*)d_in[23];
    const float* bn1_w   = (const float*)d_in[24];
    const float* bn1_b   = (const float*)d_in[25];
    const float* bn1_m   = (const float*)d_in[26];
    const float* bn1_v   = (const float*)d_in[27];
    const float* w2      = (const float*)d_in[28];
    const float* b2      = (const float*)d_in[29];

    int B = in_sizes[0] / 32768;
    size_t smem_bytes = SMEM_FLOATS * sizeof(float);   // 56KB -> 4 CTAs/SM
    cudaFuncSetAttribute(occ_fused_kernel,
                         cudaFuncAttributeMaxDynamicSharedMemorySize, (int)smem_bytes);
    occ_fused_kernel<<<B, 256, smem_bytes>>>(
        mg, w_cr, b_cr, bnr_w, bnr_b, bnr_m, bnr_v,
        q_w, q_b, k_w, k_b, v_w, v_b, gamma, ln_w, ln_b,
        w_res, b_res, bnres_w, bnres_b, bnres_m, bnres_v,
        w1, b1, bn1_w, bn1_b, bn1_m, bn1_v, w2, b2,
        (float*)d_out);
}